// round 1
// baseline (speedup 1.0000x reference)
#include <cuda_runtime.h>
#include <math.h>

#define TOKENS 4096   // B*T
#define DMODEL 2048   // NH*HD
#define TSEQ   2048
#define NHEADS 16
#define HDIM   128
#define QLATD  1024
#define KVLATD 512

// ---------------- scratch (device globals; no allocation allowed) ----------
__device__ float g_qlat[TOKENS * QLATD];   // 16.8 MB
__device__ float g_kv  [TOKENS * KVLATD]; //  8.4 MB
__device__ float g_q   [TOKENS * DMODEL]; // 33.6 MB
__device__ float g_k   [TOKENS * DMODEL];
__device__ float g_v   [TOKENS * DMODEL];
__device__ float g_ao  [TOKENS * DMODEL];

// ---------------- NT SGEMM: C[M,N] = A[M,K] * B[N,K]^T ---------------------
// 128x128x8 tile, 256 threads, 8x8 microtile (cols split 4+4 at +64 to avoid
// LDS bank conflicts). All dims here are multiples of the tile — no bounds.
__global__ __launch_bounds__(256, 2)
void sgemm_nt(const float* __restrict__ A, const float* __restrict__ B,
              float* __restrict__ C, int M, int N, int K) {
    __shared__ float As[8][128];
    __shared__ float Bs[8][128];
    const int tid = threadIdx.x;
    const int tx = tid & 15, ty = tid >> 4;
    const int bm = blockIdx.y * 128, bn = blockIdx.x * 128;
    const int lr = tid >> 1, lc = (tid & 1) << 2;
    const float* Ag = A + (size_t)(bm + lr) * K + lc;
    const float* Bg = B + (size_t)(bn + lr) * K + lc;

    float acc[8][8];
#pragma unroll
    for (int i = 0; i < 8; i++)
#pragma unroll
        for (int j = 0; j < 8; j++) acc[i][j] = 0.f;

    for (int k0 = 0; k0 < K; k0 += 8) {
        float4 av = *(const float4*)(Ag + k0);
        float4 bv = *(const float4*)(Bg + k0);
        __syncthreads();
        As[lc + 0][lr] = av.x; As[lc + 1][lr] = av.y;
        As[lc + 2][lr] = av.z; As[lc + 3][lr] = av.w;
        Bs[lc + 0][lr] = bv.x; Bs[lc + 1][lr] = bv.y;
        Bs[lc + 2][lr] = bv.z; Bs[lc + 3][lr] = bv.w;
        __syncthreads();
#pragma unroll
        for (int k = 0; k < 8; k++) {
            float4 a0 = *(const float4*)(&As[k][ty * 8]);
            float4 a1 = *(const float4*)(&As[k][ty * 8 + 4]);
            float4 b0 = *(const float4*)(&Bs[k][tx * 4]);
            float4 b1 = *(const float4*)(&Bs[k][64 + tx * 4]);
            float a[8] = {a0.x, a0.y, a0.z, a0.w, a1.x, a1.y, a1.z, a1.w};
            float b[8] = {b0.x, b0.y, b0.z, b0.w, b1.x, b1.y, b1.z, b1.w};
#pragma unroll
            for (int i = 0; i < 8; i++)
#pragma unroll
                for (int j = 0; j < 8; j++)
                    acc[i][j] += a[i] * b[j];
        }
    }
#pragma unroll
    for (int i = 0; i < 8; i++) {
        float* Cr = C + (size_t)(bm + ty * 8 + i) * N + bn;
        *(float4*)(Cr + tx * 4)      = make_float4(acc[i][0], acc[i][1], acc[i][2], acc[i][3]);
        *(float4*)(Cr + 64 + tx * 4) = make_float4(acc[i][4], acc[i][5], acc[i][6], acc[i][7]);
    }
}

// ---------------- fused per-head RMSNorm + RoPE (in place) -----------------
// one block = one (token, head); 128 threads = 128 dims
__global__ __launch_bounds__(128)
void norm_rope_kernel(float* __restrict__ X, const float* __restrict__ w) {
    const int blk = blockIdx.x;
    const int token = blk >> 4, h = blk & 15;
    const int t = token & (TSEQ - 1);   // position within sequence
    const int i = threadIdx.x;
    float* v = X + (size_t)token * DMODEL + h * HDIM;
    float x = v[i];
    float ss = x * x;
#pragma unroll
    for (int off = 16; off; off >>= 1)
        ss += __shfl_xor_sync(0xffffffffu, ss, off);
    __shared__ float sred[4];
    if ((i & 31) == 0) sred[i >> 5] = ss;
    __syncthreads();
    ss = sred[0] + sred[1] + sred[2] + sred[3];
    float rn = rsqrtf(ss * (1.0f / HDIM) + 1e-6f);
    float xn = x * rn * w[i];
    __shared__ float sh[HDIM];
    sh[i] = xn;
    __syncthreads();
    const int f = i & 63;
    // inv_freq = 10000^(-f/64) = 2^(-f/64 * log2(10000))
    float invf = exp2f((float)f * (-13.287712379549449f / 64.0f));
    float ang = (float)t * invf;
    float c, s;
    sincosf(ang, &s, &c);
    float partner = (i < 64) ? -sh[i + 64] : sh[i - 64];
    v[i] = xn * c + partner * s;
}

// ---------------- causal flash attention (fp32, online softmax) ------------
// layouts: Q/K/V/O all [B*T, NH*HD] row-major; block = (qb, b*16+h)
// BQ = BKV = 64, 256 threads. Kt stored d-major (stride 68, float4 aligned).
#define KT_STRIDE 68
#define PS_STRIDE 68
#define FA_SMEM_FLOATS (64 * 128 + 128 * KT_STRIDE + 64 * 128 + 64 * PS_STRIDE)
#define ATTN_SCALE 0.08838834764831845f   // 1/sqrt(128)

__global__ __launch_bounds__(256, 1)
void flash_kernel(const float* __restrict__ Q, const float* __restrict__ K,
                  const float* __restrict__ V, float* __restrict__ O) {
    extern __shared__ float sm[];
    float* Qs = sm;                        // [64][128]
    float* Kt = Qs + 64 * 128;             // [128][KT_STRIDE]  (d-major)
    float* Vs = Kt + 128 * KT_STRIDE;      // [64][128]
    float* Ps = Vs + 64 * 128;             // [64][PS_STRIDE]

    const int qb = blockIdx.x;
    const int pair = blockIdx.y;
    const int b = pair >> 4, h = pair & 15;
    const int tid = threadIdx.x;
    const int tx = tid & 15, ty = tid >> 4;
    const int r0 = ty * 4;
    const size_t base = (size_t)b * TSEQ * DMODEL + (size_t)h * HDIM;
    const float* Qg = Q + base + (size_t)(qb * 64) * DMODEL;

    // load Q tile (64 x 128): consecutive lanes = consecutive cols -> coalesced
#pragma unroll
    for (int i = 0; i < 8; i++) {
        int f = tid + i * 256;
        int r = f >> 5, c = (f & 31) << 2;
        *(float4*)(Qs + r * 128 + c) = *(const float4*)(Qg + (size_t)r * DMODEL + c);
    }

    float o[4][8];
    float m[4], l[4];
#pragma unroll
    for (int i = 0; i < 4; i++) {
        m[i] = -1e30f; l[i] = 0.f;
#pragma unroll
        for (int j = 0; j < 8; j++) o[i][j] = 0.f;
    }

    for (int kb = 0; kb <= qb; kb++) {          // causal: skip blocks above diag
        const float* Kg = K + base + (size_t)(kb * 64) * DMODEL;
        const float* Vg = V + base + (size_t)(kb * 64) * DMODEL;
        __syncthreads();                         // prev PV done before overwrite
#pragma unroll
        for (int i = 0; i < 8; i++) {
            int f = tid + i * 256;
            // K: transpose into Kt[d][t] (lanes -> consecutive t: conflict-free)
            int kr = f & 63, kc = (f >> 6) << 2;
            float4 k4 = *(const float4*)(Kg + (size_t)kr * DMODEL + kc);
            Kt[(kc + 0) * KT_STRIDE + kr] = k4.x;
            Kt[(kc + 1) * KT_STRIDE + kr] = k4.y;
            Kt[(kc + 2) * KT_STRIDE + kr] = k4.z;
            Kt[(kc + 3) * KT_STRIDE + kr] = k4.w;
            // V: natural layout
            int vr = f >> 5, vc = (f & 31) << 2;
            *(float4*)(Vs + vr * 128 + vc) = *(const float4*)(Vg + (size_t)vr * DMODEL + vc);
        }
        __syncthreads();

        // ---- S = (Q K^T) tile 4x4 per thread: rows r0.., cols tx*4.. ----
        float s4[4][4];
#pragma unroll
        for (int i = 0; i < 4; i++)
#pragma unroll
            for (int j = 0; j < 4; j++) s4[i][j] = 0.f;

#pragma unroll 4
        for (int k0 = 0; k0 < 128; k0 += 4) {
            float4 qv[4];
#pragma unroll
            for (int i = 0; i < 4; i++)
                qv[i] = *(const float4*)(Qs + (r0 + i) * 128 + k0);
#pragma unroll
            for (int kk = 0; kk < 4; kk++) {
                float4 kv = *(const float4*)(Kt + (size_t)(k0 + kk) * KT_STRIDE + (tx << 2));
#pragma unroll
                for (int i = 0; i < 4; i++) {
                    float q = ((const float*)&qv[i])[kk];
                    s4[i][0] += q * kv.x; s4[i][1] += q * kv.y;
                    s4[i][2] += q * kv.z; s4[i][3] += q * kv.w;
                }
            }
        }

        // ---- online softmax update ----
        const bool diag = (kb == qb);
        const int qrow = qb * 64 + r0;
        const int cbase = kb * 64 + (tx << 2);
#pragma unroll
        for (int i = 0; i < 4; i++) {
            float rmax = -1e30f;
#pragma unroll
            for (int j = 0; j < 4; j++) {
                float sv = s4[i][j] * ATTN_SCALE;
                if (diag && (cbase + j > qrow + i)) sv = -1e30f;
                s4[i][j] = sv;
                rmax = fmaxf(rmax, sv);
            }
#pragma unroll
            for (int off = 8; off; off >>= 1)
                rmax = fmaxf(rmax, __shfl_xor_sync(0xffffffffu, rmax, off));
            float mn = fmaxf(m[i], rmax);
            float alpha = expf(m[i] - mn);
            m[i] = mn;
            float rsum = 0.f;
#pragma unroll
            for (int j = 0; j < 4; j++) {
                float p = expf(s4[i][j] - mn);
                s4[i][j] = p;
                rsum += p;
            }
#pragma unroll
            for (int off = 8; off; off >>= 1)
                rsum += __shfl_xor_sync(0xffffffffu, rsum, off);
            l[i] = l[i] * alpha + rsum;
#pragma unroll
            for (int j = 0; j < 8; j++) o[i][j] *= alpha;
#pragma unroll
            for (int j = 0; j < 4; j++)
                Ps[(r0 + i) * PS_STRIDE + (tx << 2) + j] = s4[i][j];
        }
        __syncthreads();

        // ---- O += P V : cols {tx*4..+3, 64+tx*4..+3} ----
#pragma unroll 4
        for (int k0 = 0; k0 < 64; k0 += 4) {
            float4 pv[4];
#pragma unroll
            for (int i = 0; i < 4; i++)
                pv[i] = *(const float4*)(Ps + (r0 + i) * PS_STRIDE + k0);
#pragma unroll
            for (int kk = 0; kk < 4; kk++) {
                float4 v0 = *(const float4*)(Vs + (k0 + kk) * 128 + (tx << 2));
                float4 v1 = *(const float4*)(Vs + (k0 + kk) * 128 + 64 + (tx << 2));
#pragma unroll
                for (int i = 0; i < 4; i++) {
                    float p = ((const float*)&pv[i])[kk];
                    o[i][0] += p * v0.x; o[i][1] += p * v0.y;
                    o[i][2] += p * v0.z; o[i][3] += p * v0.w;
                    o[i][4] += p * v1.x; o[i][5] += p * v1.y;
                    o[i][6] += p * v1.z; o[i][7] += p * v1.w;
                }
            }
        }
    }

    // ---- normalize + store (back to [token][h*128+d] layout) ----
    float* Og = O + base + (size_t)(qb * 64) * DMODEL;
#pragma unroll
    for (int i = 0; i < 4; i++) {
        float inv = 1.f / l[i];
        *(float4*)(Og + (size_t)(r0 + i) * DMODEL + (tx << 2)) =
            make_float4(o[i][0] * inv, o[i][1] * inv, o[i][2] * inv, o[i][3] * inv);
        *(float4*)(Og + (size_t)(r0 + i) * DMODEL + 64 + (tx << 2)) =
            make_float4(o[i][4] * inv, o[i][5] * inv, o[i][6] * inv, o[i][7] * inv);
    }
}

// ---------------- launch ----------------------------------------------------
extern "C" void kernel_launch(void* const* d_in, const int* in_sizes, int n_in,
                              void* d_out, int out_size) {
    const float* x      = (const float*)d_in[0];
    // d_in[1] = attn_mask (causal; applied analytically)
    const float* q_a_w  = (const float*)d_in[2];
    const float* q_b_w  = (const float*)d_in[3];
    const float* kv_a_w = (const float*)d_in[4];
    const float* k_b_w  = (const float*)d_in[5];
    const float* v_b_w  = (const float*)d_in[6];
    const float* o_w    = (const float*)d_in[7];
    const float* q_nw   = (const float*)d_in[8];
    const float* k_nw   = (const float*)d_in[9];

    float *qlat, *kv, *q, *k, *v, *ao;
    cudaGetSymbolAddress((void**)&qlat, g_qlat);
    cudaGetSymbolAddress((void**)&kv,   g_kv);
    cudaGetSymbolAddress((void**)&q,    g_q);
    cudaGetSymbolAddress((void**)&k,    g_k);
    cudaGetSymbolAddress((void**)&v,    g_v);
    cudaGetSymbolAddress((void**)&ao,   g_ao);

    // projections
    sgemm_nt<<<dim3(QLATD / 128, TOKENS / 128), 256>>>(x, q_a_w, qlat, TOKENS, QLATD, DMODEL);
    sgemm_nt<<<dim3(DMODEL / 128, TOKENS / 128), 256>>>(qlat, q_b_w, q, TOKENS, DMODEL, QLATD);
    sgemm_nt<<<dim3(KVLATD / 128, TOKENS / 128), 256>>>(x, kv_a_w, kv, TOKENS, KVLATD, DMODEL);
    sgemm_nt<<<dim3(DMODEL / 128, TOKENS / 128), 256>>>(kv, k_b_w, k, TOKENS, DMODEL, KVLATD);
    sgemm_nt<<<dim3(DMODEL / 128, TOKENS / 128), 256>>>(kv, v_b_w, v, TOKENS, DMODEL, KVLATD);

    // per-head RMSNorm + RoPE
    norm_rope_kernel<<<TOKENS * NHEADS, 128>>>(q, q_nw);
    norm_rope_kernel<<<TOKENS * NHEADS, 128>>>(k, k_nw);

    // causal flash attention
    static const int fa_smem = FA_SMEM_FLOATS * (int)sizeof(float);
    cudaFuncSetAttribute(flash_kernel, cudaFuncAttributeMaxDynamicSharedMemorySize, fa_smem);
    flash_kernel<<<dim3(TSEQ / 64, 2 * NHEADS), 256, fa_smem>>>(q, k, v, ao);

    // output projection -> d_out
    sgemm_nt<<<dim3(DMODEL / 128, TOKENS / 128), 256>>>(ao, o_w, (float*)d_out, TOKENS, DMODEL, DMODEL);
}

// round 3
// speedup vs baseline: 1.4332x; 1.4332x over previous
#include <cuda_runtime.h>
#include <cuda_bf16.h>
#include <math.h>
#include <cstdint>

#define TOKENS 4096   // B*T
#define DMODEL 2048   // NH*HD
#define TSEQ   2048
#define NHEADS 16
#define HDIM   128
#define QLATD  1024
#define KVLATD 512

// ---------------- scratch (device globals; no allocation allowed) ----------
__device__ float g_q  [TOKENS * DMODEL];
__device__ float g_k  [TOKENS * DMODEL];
__device__ float g_v  [TOKENS * DMODEL];
__device__ float g_ao [TOKENS * DMODEL];
// bf16 hi/lo split operands
__device__ __nv_bfloat16 g_xh [TOKENS * DMODEL],  g_xl [TOKENS * DMODEL];
__device__ __nv_bfloat16 g_qlh[TOKENS * QLATD],   g_qll[TOKENS * QLATD];
__device__ __nv_bfloat16 g_kvh[TOKENS * KVLATD],  g_kvl[TOKENS * KVLATD];
__device__ __nv_bfloat16 g_aoh[TOKENS * DMODEL],  g_aol[TOKENS * DMODEL];
__device__ __nv_bfloat16 g_wqah[QLATD * DMODEL],  g_wqal[QLATD * DMODEL];
__device__ __nv_bfloat16 g_wqbh[DMODEL * QLATD],  g_wqbl[DMODEL * QLATD];
__device__ __nv_bfloat16 g_wkvh[KVLATD * DMODEL], g_wkvl[KVLATD * DMODEL];
__device__ __nv_bfloat16 g_wkbh[DMODEL * KVLATD], g_wkbl[DMODEL * KVLATD];
__device__ __nv_bfloat16 g_wvbh[DMODEL * KVLATD], g_wvbl[DMODEL * KVLATD];
__device__ __nv_bfloat16 g_owh [DMODEL * DMODEL], g_owl [DMODEL * DMODEL];

// ================= warp-mma helpers (baseline PTX, no "a"-features) ========
__device__ __forceinline__ uint32_t smem_u32(const void* p) {
    uint32_t a;
    asm("{ .reg .u64 t; cvta.to.shared.u64 t, %1; cvt.u32.u64 %0, t; }"
        : "=r"(a) : "l"(p));
    return a;
}

#define LDM4(r, addr) \
    asm volatile("ldmatrix.sync.aligned.m8n8.x4.shared.b16 {%0,%1,%2,%3}, [%4];" \
                 : "=r"((r)[0]), "=r"((r)[1]), "=r"((r)[2]), "=r"((r)[3]) : "r"(addr))
#define LDM2(r, addr) \
    asm volatile("ldmatrix.sync.aligned.m8n8.x2.shared.b16 {%0,%1}, [%2];" \
                 : "=r"((r)[0]), "=r"((r)[1]) : "r"(addr))
#define MMA_BF16(d, a, b) \
    asm volatile("mma.sync.aligned.m16n8k16.row.col.f32.bf16.bf16.f32 " \
                 "{%0,%1,%2,%3}, {%4,%5,%6,%7}, {%8,%9}, {%0,%1,%2,%3};" \
                 : "+f"((d)[0]), "+f"((d)[1]), "+f"((d)[2]), "+f"((d)[3]) \
                 : "r"((a)[0]), "r"((a)[1]), "r"((a)[2]), "r"((a)[3]), \
                   "r"((b)[0]), "r"((b)[1]))

// ============= tensor-core GEMM: C[M,N] = (Ah+Al)[M,K] * (Bh+Bl)[N,K]^T ====
// 128x128 block tile, BK=32, 8 warps each 64x32 (warp grid 2m x 4n).
// 3-term bf16 split: C = Ah*Bh + Ah*Bl + Al*Bh (fp32 accum).
// Epilogue: fp32 C (Cf) and/or bf16 hi/lo (Ch, Cl).
#define SSTR 40   // smem row stride in bf16 (32 + 8 pad): conflict-free ldmatrix

__global__ __launch_bounds__(256)
void gemm_mma(const __nv_bfloat16* __restrict__ Ah, const __nv_bfloat16* __restrict__ Al,
              const __nv_bfloat16* __restrict__ Bh, const __nv_bfloat16* __restrict__ Bl,
              float* __restrict__ Cf, __nv_bfloat16* __restrict__ Ch,
              __nv_bfloat16* __restrict__ Cl, int M, int N, int K) {
    __shared__ __nv_bfloat16 sAh[128 * SSTR], sAl[128 * SSTR];
    __shared__ __nv_bfloat16 sBh[128 * SSTR], sBl[128 * SSTR];

    const int tid = threadIdx.x, lane = tid & 31, warp = tid >> 5;
    const int wm = (warp & 1) * 64;        // warp m offset in tile
    const int wn = (warp >> 1) * 32;       // warp n offset in tile
    const int bm = blockIdx.y * 128, bn = blockIdx.x * 128;

    const uint32_t aAh = smem_u32(sAh), aAl = smem_u32(sAl);
    const uint32_t aBh = smem_u32(sBh), aBl = smem_u32(sBl);

    // ldmatrix per-lane source rows
    const int lrA = lane & 15, lcA = (lane >> 4) << 3;            // A: x4 tiles
    const int lB = lane & 15;
    const int lrB = lB & 7, lcB = ((lB >> 3) & 1) << 3;           // B: x2 tiles

    float c[4][4][4];
#pragma unroll
    for (int i = 0; i < 4; i++)
#pragma unroll
        for (int j = 0; j < 4; j++)
#pragma unroll
            for (int k = 0; k < 4; k++) c[i][j][k] = 0.f;

    for (int kt = 0; kt < K; kt += 32) {
        __syncthreads();
#pragma unroll
        for (int i = 0; i < 2; i++) {
            int idx = tid + i * 256;                 // 0..511
            int row = idx >> 2, cc = (idx & 3) << 3; // 8 bf16 = 16B per chunk
            size_t gA = (size_t)(bm + row) * K + kt + cc;
            size_t gB = (size_t)(bn + row) * K + kt + cc;
            int so = row * SSTR + cc;
            *(uint4*)&sAh[so] = *(const uint4*)(Ah + gA);
            *(uint4*)&sAl[so] = *(const uint4*)(Al + gA);
            *(uint4*)&sBh[so] = *(const uint4*)(Bh + gB);
            *(uint4*)&sBl[so] = *(const uint4*)(Bl + gB);
        }
        __syncthreads();

#pragma unroll
        for (int ks = 0; ks < 32; ks += 16) {
            uint32_t bh[4][2], bl[4][2];
#pragma unroll
            for (int nt = 0; nt < 4; nt++) {
                uint32_t off = (uint32_t)(((wn + nt * 8 + lrB) * SSTR + ks + lcB) * 2);
                LDM2(bh[nt], aBh + off);
                LDM2(bl[nt], aBl + off);
            }
#pragma unroll
            for (int mt = 0; mt < 4; mt++) {
                uint32_t off = (uint32_t)(((wm + mt * 16 + lrA) * SSTR + ks + lcA) * 2);
                uint32_t ah[4], al[4];
                LDM4(ah, aAh + off);
                LDM4(al, aAl + off);
#pragma unroll
                for (int nt = 0; nt < 4; nt++) {
                    MMA_BF16(c[mt][nt], ah, bh[nt]);
                    MMA_BF16(c[mt][nt], ah, bl[nt]);
                    MMA_BF16(c[mt][nt], al, bh[nt]);
                }
            }
        }
    }

    // epilogue: fragment (mt,nt): rows bm+wm+mt*16+{lane/4, +8}, cols bn+wn+nt*8+2*(lane%4)
    const int er = lane >> 2, ec = (lane & 3) << 1;
#pragma unroll
    for (int mt = 0; mt < 4; mt++) {
#pragma unroll
        for (int nt = 0; nt < 4; nt++) {
            size_t r0 = (size_t)(bm + wm + mt * 16 + er);
            int c0 = bn + wn + nt * 8 + ec;
            float v0 = c[mt][nt][0], v1 = c[mt][nt][1];
            float v2 = c[mt][nt][2], v3 = c[mt][nt][3];
            if (Cf) {
                *(float2*)(Cf + r0 * N + c0)       = make_float2(v0, v1);
                *(float2*)(Cf + (r0 + 8) * N + c0) = make_float2(v2, v3);
            }
            if (Ch) {
                __nv_bfloat16 h0 = __float2bfloat16_rn(v0), h1 = __float2bfloat16_rn(v1);
                __nv_bfloat16 h2 = __float2bfloat16_rn(v2), h3 = __float2bfloat16_rn(v3);
                __nv_bfloat16 l0 = __float2bfloat16_rn(v0 - __bfloat162float(h0));
                __nv_bfloat16 l1 = __float2bfloat16_rn(v1 - __bfloat162float(h1));
                __nv_bfloat16 l2 = __float2bfloat16_rn(v2 - __bfloat162float(h2));
                __nv_bfloat16 l3 = __float2bfloat16_rn(v3 - __bfloat162float(h3));
                *(__nv_bfloat162*)(Ch + r0 * N + c0)       = __nv_bfloat162(h0, h1);
                *(__nv_bfloat162*)(Ch + (r0 + 8) * N + c0) = __nv_bfloat162(h2, h3);
                *(__nv_bfloat162*)(Cl + r0 * N + c0)       = __nv_bfloat162(l0, l1);
                *(__nv_bfloat162*)(Cl + (r0 + 8) * N + c0) = __nv_bfloat162(l2, l3);
            }
        }
    }
}

// ---------------- fp32 -> (bf16 hi, bf16 lo) ------------------------------
__global__ __launch_bounds__(256)
void conv_hilo(const float* __restrict__ in, __nv_bfloat16* __restrict__ hi,
               __nv_bfloat16* __restrict__ lo, int n4) {
    int i = blockIdx.x * 256 + threadIdx.x;
    if (i >= n4) return;
    float4 x = ((const float4*)in)[i];
    float v[4] = {x.x, x.y, x.z, x.w};
    __nv_bfloat16 h[4], l[4];
#pragma unroll
    for (int j = 0; j < 4; j++) {
        h[j] = __float2bfloat16_rn(v[j]);
        l[j] = __float2bfloat16_rn(v[j] - __bfloat162float(h[j]));
    }
    ((__nv_bfloat162*)hi)[i * 2]     = __nv_bfloat162(h[0], h[1]);
    ((__nv_bfloat162*)hi)[i * 2 + 1] = __nv_bfloat162(h[2], h[3]);
    ((__nv_bfloat162*)lo)[i * 2]     = __nv_bfloat162(l[0], l[1]);
    ((__nv_bfloat162*)lo)[i * 2 + 1] = __nv_bfloat162(l[2], l[3]);
}

// ---------------- fused per-head RMSNorm + RoPE (in place) -----------------
__global__ __launch_bounds__(128)
void norm_rope_kernel(float* __restrict__ X, const float* __restrict__ w) {
    const int blk = blockIdx.x;
    const int token = blk >> 4, h = blk & 15;
    const int t = token & (TSEQ - 1);
    const int i = threadIdx.x;
    float* v = X + (size_t)token * DMODEL + h * HDIM;
    float x = v[i];
    float ss = x * x;
#pragma unroll
    for (int off = 16; off; off >>= 1)
        ss += __shfl_xor_sync(0xffffffffu, ss, off);
    __shared__ float sred[4];
    if ((i & 31) == 0) sred[i >> 5] = ss;
    __syncthreads();
    ss = sred[0] + sred[1] + sred[2] + sred[3];
    float rn = rsqrtf(ss * (1.0f / HDIM) + 1e-6f);
    float xn = x * rn * w[i];
    __shared__ float sh[HDIM];
    sh[i] = xn;
    __syncthreads();
    const int f = i & 63;
    float invf = exp2f((float)f * (-13.287712379549449f / 64.0f));
    float ang = (float)t * invf;
    float c, s;
    sincosf(ang, &s, &c);
    float partner = (i < 64) ? -sh[i + 64] : sh[i - 64];
    v[i] = xn * c + partner * s;
}

// ---------------- causal flash attention (fp32, online softmax) ------------
#define KT_STRIDE 68
#define PS_STRIDE 68
#define FA_SMEM_FLOATS (64 * 128 + 128 * KT_STRIDE + 64 * 128 + 64 * PS_STRIDE)
#define ATTN_SCALE 0.08838834764831845f

__global__ __launch_bounds__(256, 1)
void flash_kernel(const float* __restrict__ Q, const float* __restrict__ K,
                  const float* __restrict__ V, float* __restrict__ O) {
    extern __shared__ float sm[];
    float* Qs = sm;
    float* Kt = Qs + 64 * 128;
    float* Vs = Kt + 128 * KT_STRIDE;
    float* Ps = Vs + 64 * 128;

    const int qb = blockIdx.x;
    const int pair = blockIdx.y;
    const int b = pair >> 4, h = pair & 15;
    const int tid = threadIdx.x;
    const int tx = tid & 15, ty = tid >> 4;
    const int r0 = ty * 4;
    const size_t base = (size_t)b * TSEQ * DMODEL + (size_t)h * HDIM;
    const float* Qg = Q + base + (size_t)(qb * 64) * DMODEL;

#pragma unroll
    for (int i = 0; i < 8; i++) {
        int f = tid + i * 256;
        int r = f >> 5, c = (f & 31) << 2;
        *(float4*)(Qs + r * 128 + c) = *(const float4*)(Qg + (size_t)r * DMODEL + c);
    }

    float o[4][8];
    float m[4], l[4];
#pragma unroll
    for (int i = 0; i < 4; i++) {
        m[i] = -1e30f; l[i] = 0.f;
#pragma unroll
        for (int j = 0; j < 8; j++) o[i][j] = 0.f;
    }

    for (int kb = 0; kb <= qb; kb++) {
        const float* Kg = K + base + (size_t)(kb * 64) * DMODEL;
        const float* Vg = V + base + (size_t)(kb * 64) * DMODEL;
        __syncthreads();
#pragma unroll
        for (int i = 0; i < 8; i++) {
            int f = tid + i * 256;
            int kr = f & 63, kc = (f >> 6) << 2;
            float4 k4 = *(const float4*)(Kg + (size_t)kr * DMODEL + kc);
            Kt[(kc + 0) * KT_STRIDE + kr] = k4.x;
            Kt[(kc + 1) * KT_STRIDE + kr] = k4.y;
            Kt[(kc + 2) * KT_STRIDE + kr] = k4.z;
            Kt[(kc + 3) * KT_STRIDE + kr] = k4.w;
            int vr = f >> 5, vc = (f & 31) << 2;
            *(float4*)(Vs + vr * 128 + vc) = *(const float4*)(Vg + (size_t)vr * DMODEL + vc);
        }
        __syncthreads();

        float s4[4][4];
#pragma unroll
        for (int i = 0; i < 4; i++)
#pragma unroll
            for (int j = 0; j < 4; j++) s4[i][j] = 0.f;

#pragma unroll 4
        for (int k0 = 0; k0 < 128; k0 += 4) {
            float4 qv[4];
#pragma unroll
            for (int i = 0; i < 4; i++)
                qv[i] = *(const float4*)(Qs + (r0 + i) * 128 + k0);
#pragma unroll
            for (int kk = 0; kk < 4; kk++) {
                float4 kv = *(const float4*)(Kt + (size_t)(k0 + kk) * KT_STRIDE + (tx << 2));
#pragma unroll
                for (int i = 0; i < 4; i++) {
                    float q = ((const float*)&qv[i])[kk];
                    s4[i][0] += q * kv.x; s4[i][1] += q * kv.y;
                    s4[i][2] += q * kv.z; s4[i][3] += q * kv.w;
                }
            }
        }

        const bool diag = (kb == qb);
        const int qrow = qb * 64 + r0;
        const int cbase = kb * 64 + (tx << 2);
#pragma unroll
        for (int i = 0; i < 4; i++) {
            float rmax = -1e30f;
#pragma unroll
            for (int j = 0; j < 4; j++) {
                float sv = s4[i][j] * ATTN_SCALE;
                if (diag && (cbase + j > qrow + i)) sv = -1e30f;
                s4[i][j] = sv;
                rmax = fmaxf(rmax, sv);
            }
#pragma unroll
            for (int off = 8; off; off >>= 1)
                rmax = fmaxf(rmax, __shfl_xor_sync(0xffffffffu, rmax, off));
            float mn = fmaxf(m[i], rmax);
            float alpha = expf(m[i] - mn);
            m[i] = mn;
            float rsum = 0.f;
#pragma unroll
            for (int j = 0; j < 4; j++) {
                float p = expf(s4[i][j] - mn);
                s4[i][j] = p;
                rsum += p;
            }
#pragma unroll
            for (int off = 8; off; off >>= 1)
                rsum += __shfl_xor_sync(0xffffffffu, rsum, off);
            l[i] = l[i] * alpha + rsum;
#pragma unroll
            for (int j = 0; j < 8; j++) o[i][j] *= alpha;
#pragma unroll
            for (int j = 0; j < 4; j++)
                Ps[(r0 + i) * PS_STRIDE + (tx << 2) + j] = s4[i][j];
        }
        __syncthreads();

#pragma unroll 4
        for (int k0 = 0; k0 < 64; k0 += 4) {
            float4 pv[4];
#pragma unroll
            for (int i = 0; i < 4; i++)
                pv[i] = *(const float4*)(Ps + (r0 + i) * PS_STRIDE + k0);
#pragma unroll
            for (int kk = 0; kk < 4; kk++) {
                float4 v0 = *(const float4*)(Vs + (k0 + kk) * 128 + (tx << 2));
                float4 v1 = *(const float4*)(Vs + (k0 + kk) * 128 + 64 + (tx << 2));
#pragma unroll
                for (int i = 0; i < 4; i++) {
                    float p = ((const float*)&pv[i])[kk];
                    o[i][0] += p * v0.x; o[i][1] += p * v0.y;
                    o[i][2] += p * v0.z; o[i][3] += p * v0.w;
                    o[i][4] += p * v1.x; o[i][5] += p * v1.y;
                    o[i][6] += p * v1.z; o[i][7] += p * v1.w;
                }
            }
        }
    }

    float* Og = O + base + (size_t)(qb * 64) * DMODEL;
#pragma unroll
    for (int i = 0; i < 4; i++) {
        float inv = 1.f / l[i];
        *(float4*)(Og + (size_t)(r0 + i) * DMODEL + (tx << 2)) =
            make_float4(o[i][0] * inv, o[i][1] * inv, o[i][2] * inv, o[i][3] * inv);
        *(float4*)(Og + (size_t)(r0 + i) * DMODEL + 64 + (tx << 2)) =
            make_float4(o[i][4] * inv, o[i][5] * inv, o[i][6] * inv, o[i][7] * inv);
    }
}

// ---------------- launch ----------------------------------------------------
static inline void conv(const float* in, __nv_bfloat16* h, __nv_bfloat16* l, int n) {
    int n4 = n / 4;
    conv_hilo<<<(n4 + 255) / 256, 256>>>(in, h, l, n4);
}

extern "C" void kernel_launch(void* const* d_in, const int* in_sizes, int n_in,
                              void* d_out, int out_size) {
    const float* x      = (const float*)d_in[0];
    const float* q_a_w  = (const float*)d_in[2];
    const float* q_b_w  = (const float*)d_in[3];
    const float* kv_a_w = (const float*)d_in[4];
    const float* k_b_w  = (const float*)d_in[5];
    const float* v_b_w  = (const float*)d_in[6];
    const float* o_w    = (const float*)d_in[7];
    const float* q_nw   = (const float*)d_in[8];
    const float* k_nw   = (const float*)d_in[9];

    float *q, *k, *v, *ao;
    __nv_bfloat16 *xh, *xl, *qlh, *qll, *kvh, *kvl, *aoh, *aol;
    __nv_bfloat16 *wqah, *wqal, *wqbh, *wqbl, *wkvh, *wkvl, *wkbh, *wkbl, *wvbh, *wvbl, *owh, *owl;
    cudaGetSymbolAddress((void**)&q, g_q);     cudaGetSymbolAddress((void**)&k, g_k);
    cudaGetSymbolAddress((void**)&v, g_v);     cudaGetSymbolAddress((void**)&ao, g_ao);
    cudaGetSymbolAddress((void**)&xh, g_xh);   cudaGetSymbolAddress((void**)&xl, g_xl);
    cudaGetSymbolAddress((void**)&qlh, g_qlh); cudaGetSymbolAddress((void**)&qll, g_qll);
    cudaGetSymbolAddress((void**)&kvh, g_kvh); cudaGetSymbolAddress((void**)&kvl, g_kvl);
    cudaGetSymbolAddress((void**)&aoh, g_aoh); cudaGetSymbolAddress((void**)&aol, g_aol);
    cudaGetSymbolAddress((void**)&wqah, g_wqah); cudaGetSymbolAddress((void**)&wqal, g_wqal);
    cudaGetSymbolAddress((void**)&wqbh, g_wqbh); cudaGetSymbolAddress((void**)&wqbl, g_wqbl);
    cudaGetSymbolAddress((void**)&wkvh, g_wkvh); cudaGetSymbolAddress((void**)&wkvl, g_wkvl);
    cudaGetSymbolAddress((void**)&wkbh, g_wkbh); cudaGetSymbolAddress((void**)&wkbl, g_wkbl);
    cudaGetSymbolAddress((void**)&wvbh, g_wvbh); cudaGetSymbolAddress((void**)&wvbl, g_wvbl);
    cudaGetSymbolAddress((void**)&owh, g_owh);   cudaGetSymbolAddress((void**)&owl, g_owl);

    static const int fa_smem = FA_SMEM_FLOATS * (int)sizeof(float);
    cudaFuncSetAttribute(flash_kernel, cudaFuncAttributeMaxDynamicSharedMemorySize, fa_smem);

    // fp32 -> bf16 hi/lo conversions
    conv(x, xh, xl, TOKENS * DMODEL);
    conv(q_a_w, wqah, wqal, QLATD * DMODEL);
    conv(q_b_w, wqbh, wqbl, DMODEL * QLATD);
    conv(kv_a_w, wkvh, wkvl, KVLATD * DMODEL);
    conv(k_b_w, wkbh, wkbl, DMODEL * KVLATD);
    conv(v_b_w, wvbh, wvbl, DMODEL * KVLATD);
    conv(o_w, owh, owl, DMODEL * DMODEL);

    // projections on HMMA (3-term bf16 split)
    gemm_mma<<<dim3(QLATD / 128, TOKENS / 128), 256>>>(
        xh, xl, wqah, wqal, nullptr, qlh, qll, TOKENS, QLATD, DMODEL);
    gemm_mma<<<dim3(DMODEL / 128, TOKENS / 128), 256>>>(
        qlh, qll, wqbh, wqbl, q, nullptr, nullptr, TOKENS, DMODEL, QLATD);
    gemm_mma<<<dim3(KVLATD / 128, TOKENS / 128), 256>>>(
        xh, xl, wkvh, wkvl, nullptr, kvh, kvl, TOKENS, KVLATD, DMODEL);
    gemm_mma<<<dim3(DMODEL / 128, TOKENS / 128), 256>>>(
        kvh, kvl, wkbh, wkbl, k, nullptr, nullptr, TOKENS, DMODEL, KVLATD);
    gemm_mma<<<dim3(DMODEL / 128, TOKENS / 128), 256>>>(
        kvh, kvl, wvbh, wvbl, v, nullptr, nullptr, TOKENS, DMODEL, KVLATD);

    // per-head RMSNorm + RoPE
    norm_rope_kernel<<<TOKENS * NHEADS, 128>>>(q, q_nw);
    norm_rope_kernel<<<TOKENS * NHEADS, 128>>>(k, k_nw);

    // causal flash attention (fp32)
    flash_kernel<<<dim3(TSEQ / 64, 2 * NHEADS), 256, fa_smem>>>(q, k, v, ao);

    // output projection
    conv(ao, aoh, aol, TOKENS * DMODEL);
    gemm_mma<<<dim3(DMODEL / 128, TOKENS / 128), 256>>>(
        aoh, aol, owh, owl, (float*)d_out, nullptr, nullptr, TOKENS, DMODEL, DMODEL);
}

// round 4
// speedup vs baseline: 1.9861x; 1.3858x over previous
#include <cuda_runtime.h>
#include <cuda_bf16.h>
#include <math.h>
#include <cstdint>

#define TOKENS 4096   // B*T
#define DMODEL 2048   // NH*HD
#define TSEQ   2048
#define NHEADS 16
#define HDIM   128
#define QLATD  1024
#define KVLATD 512

typedef __nv_bfloat16 bf16;

// ---------------- scratch (device globals; no allocation allowed) ----------
__device__ float g_q  [TOKENS * DMODEL];
__device__ float g_k  [TOKENS * DMODEL];
// bf16 hi/lo split operands
__device__ bf16 g_xh [TOKENS * DMODEL],  g_xl [TOKENS * DMODEL];
__device__ bf16 g_qlh[TOKENS * QLATD],   g_qll[TOKENS * QLATD];
__device__ bf16 g_kvh[TOKENS * KVLATD],  g_kvl[TOKENS * KVLATD];
__device__ bf16 g_qh [TOKENS * DMODEL],  g_ql [TOKENS * DMODEL];
__device__ bf16 g_kh [TOKENS * DMODEL],  g_kl [TOKENS * DMODEL];
__device__ bf16 g_vh [TOKENS * DMODEL],  g_vl [TOKENS * DMODEL];
__device__ bf16 g_aoh[TOKENS * DMODEL],  g_aol[TOKENS * DMODEL];
__device__ bf16 g_wqah[QLATD * DMODEL],  g_wqal[QLATD * DMODEL];
__device__ bf16 g_wqbh[DMODEL * QLATD],  g_wqbl[DMODEL * QLATD];
__device__ bf16 g_wkvh[KVLATD * DMODEL], g_wkvl[KVLATD * DMODEL];
__device__ bf16 g_wkbh[DMODEL * KVLATD], g_wkbl[DMODEL * KVLATD];
__device__ bf16 g_wvbh[DMODEL * KVLATD], g_wvbl[DMODEL * KVLATD];
__device__ bf16 g_owh [DMODEL * DMODEL], g_owl [DMODEL * DMODEL];

// ================= warp-mma helpers (baseline PTX, no "a"-features) ========
__device__ __forceinline__ uint32_t smem_u32(const void* p) {
    uint32_t a;
    asm("{ .reg .u64 t; cvta.to.shared.u64 t, %1; cvt.u32.u64 %0, t; }"
        : "=r"(a) : "l"(p));
    return a;
}
__device__ __forceinline__ float ex2(float x) {
    float y;
    asm("ex2.approx.ftz.f32 %0, %1;" : "=f"(y) : "f"(x));
    return y;
}

#define LDM4(r, addr) \
    asm volatile("ldmatrix.sync.aligned.m8n8.x4.shared.b16 {%0,%1,%2,%3}, [%4];" \
                 : "=r"((r)[0]), "=r"((r)[1]), "=r"((r)[2]), "=r"((r)[3]) : "r"(addr))
#define LDM2(r, addr) \
    asm volatile("ldmatrix.sync.aligned.m8n8.x2.shared.b16 {%0,%1}, [%2];" \
                 : "=r"((r)[0]), "=r"((r)[1]) : "r"(addr))
#define LDM2T(r, addr) \
    asm volatile("ldmatrix.sync.aligned.m8n8.x2.trans.shared.b16 {%0,%1}, [%2];" \
                 : "=r"((r)[0]), "=r"((r)[1]) : "r"(addr))
#define MMA_BF16(d, a, b) \
    asm volatile("mma.sync.aligned.m16n8k16.row.col.f32.bf16.bf16.f32 " \
                 "{%0,%1,%2,%3}, {%4,%5,%6,%7}, {%8,%9}, {%0,%1,%2,%3};" \
                 : "+f"((d)[0]), "+f"((d)[1]), "+f"((d)[2]), "+f"((d)[3]) \
                 : "r"((a)[0]), "r"((a)[1]), "r"((a)[2]), "r"((a)[3]), \
                   "r"((b)[0]), "r"((b)[1]))

__device__ __forceinline__ void split2(float v, bf16& h, bf16& l) {
    h = __float2bfloat16_rn(v);
    l = __float2bfloat16_rn(v - __bfloat162float(h));
}

// ============= tensor-core GEMM: C[M,N] = (Ah+Al)[M,K] * (Bh+Bl)[N,K]^T ====
#define SSTR 40

__global__ __launch_bounds__(256)
void gemm_mma(const bf16* __restrict__ Ah, const bf16* __restrict__ Al,
              const bf16* __restrict__ Bh, const bf16* __restrict__ Bl,
              float* __restrict__ Cf, bf16* __restrict__ Ch,
              bf16* __restrict__ Cl, int M, int N, int K) {
    __shared__ bf16 sAh[128 * SSTR], sAl[128 * SSTR];
    __shared__ bf16 sBh[128 * SSTR], sBl[128 * SSTR];

    const int tid = threadIdx.x, lane = tid & 31, warp = tid >> 5;
    const int wm = (warp & 1) * 64;
    const int wn = (warp >> 1) * 32;
    const int bm = blockIdx.y * 128, bn = blockIdx.x * 128;

    const uint32_t aAh = smem_u32(sAh), aAl = smem_u32(sAl);
    const uint32_t aBh = smem_u32(sBh), aBl = smem_u32(sBl);

    const int lrA = lane & 15, lcA = (lane >> 4) << 3;
    const int lB = lane & 15;
    const int lrB = lB & 7, lcB = ((lB >> 3) & 1) << 3;

    float c[4][4][4];
#pragma unroll
    for (int i = 0; i < 4; i++)
#pragma unroll
        for (int j = 0; j < 4; j++)
#pragma unroll
            for (int k = 0; k < 4; k++) c[i][j][k] = 0.f;

    for (int kt = 0; kt < K; kt += 32) {
        __syncthreads();
#pragma unroll
        for (int i = 0; i < 2; i++) {
            int idx = tid + i * 256;
            int row = idx >> 2, cc = (idx & 3) << 3;
            size_t gA = (size_t)(bm + row) * K + kt + cc;
            size_t gB = (size_t)(bn + row) * K + kt + cc;
            int so = row * SSTR + cc;
            *(uint4*)&sAh[so] = *(const uint4*)(Ah + gA);
            *(uint4*)&sAl[so] = *(const uint4*)(Al + gA);
            *(uint4*)&sBh[so] = *(const uint4*)(Bh + gB);
            *(uint4*)&sBl[so] = *(const uint4*)(Bl + gB);
        }
        __syncthreads();

#pragma unroll
        for (int ks = 0; ks < 32; ks += 16) {
            uint32_t bh[4][2], bl[4][2];
#pragma unroll
            for (int nt = 0; nt < 4; nt++) {
                uint32_t off = (uint32_t)(((wn + nt * 8 + lrB) * SSTR + ks + lcB) * 2);
                LDM2(bh[nt], aBh + off);
                LDM2(bl[nt], aBl + off);
            }
#pragma unroll
            for (int mt = 0; mt < 4; mt++) {
                uint32_t off = (uint32_t)(((wm + mt * 16 + lrA) * SSTR + ks + lcA) * 2);
                uint32_t ah[4], al[4];
                LDM4(ah, aAh + off);
                LDM4(al, aAl + off);
#pragma unroll
                for (int nt = 0; nt < 4; nt++) {
                    MMA_BF16(c[mt][nt], ah, bh[nt]);
                    MMA_BF16(c[mt][nt], ah, bl[nt]);
                    MMA_BF16(c[mt][nt], al, bh[nt]);
                }
            }
        }
    }

    const int er = lane >> 2, ec = (lane & 3) << 1;
#pragma unroll
    for (int mt = 0; mt < 4; mt++) {
#pragma unroll
        for (int nt = 0; nt < 4; nt++) {
            size_t r0 = (size_t)(bm + wm + mt * 16 + er);
            int c0 = bn + wn + nt * 8 + ec;
            float v0 = c[mt][nt][0], v1 = c[mt][nt][1];
            float v2 = c[mt][nt][2], v3 = c[mt][nt][3];
            if (Cf) {
                *(float2*)(Cf + r0 * N + c0)       = make_float2(v0, v1);
                *(float2*)(Cf + (r0 + 8) * N + c0) = make_float2(v2, v3);
            }
            if (Ch) {
                bf16 h0, l0, h1, l1, h2, l2, h3, l3;
                split2(v0, h0, l0); split2(v1, h1, l1);
                split2(v2, h2, l2); split2(v3, h3, l3);
                *(__nv_bfloat162*)(Ch + r0 * N + c0)       = __nv_bfloat162(h0, h1);
                *(__nv_bfloat162*)(Ch + (r0 + 8) * N + c0) = __nv_bfloat162(h2, h3);
                *(__nv_bfloat162*)(Cl + r0 * N + c0)       = __nv_bfloat162(l0, l1);
                *(__nv_bfloat162*)(Cl + (r0 + 8) * N + c0) = __nv_bfloat162(l2, l3);
            }
        }
    }
}

// ---------------- fp32 -> (bf16 hi, bf16 lo) ------------------------------
__global__ __launch_bounds__(256)
void conv_hilo(const float* __restrict__ in, bf16* __restrict__ hi,
               bf16* __restrict__ lo, int n4) {
    int i = blockIdx.x * 256 + threadIdx.x;
    if (i >= n4) return;
    float4 x = ((const float4*)in)[i];
    float v[4] = {x.x, x.y, x.z, x.w};
    bf16 h[4], l[4];
#pragma unroll
    for (int j = 0; j < 4; j++) split2(v[j], h[j], l[j]);
    ((__nv_bfloat162*)hi)[i * 2]     = __nv_bfloat162(h[0], h[1]);
    ((__nv_bfloat162*)hi)[i * 2 + 1] = __nv_bfloat162(h[2], h[3]);
    ((__nv_bfloat162*)lo)[i * 2]     = __nv_bfloat162(l[0], l[1]);
    ((__nv_bfloat162*)lo)[i * 2 + 1] = __nv_bfloat162(l[2], l[3]);
}

// -------- fused per-head RMSNorm + RoPE, emitting bf16 hi/lo ---------------
__global__ __launch_bounds__(128)
void norm_rope_kernel(const float* __restrict__ X, const float* __restrict__ w,
                      bf16* __restrict__ H, bf16* __restrict__ L) {
    const int blk = blockIdx.x;
    const int token = blk >> 4, h = blk & 15;
    const int t = token & (TSEQ - 1);
    const int i = threadIdx.x;
    const size_t off = (size_t)token * DMODEL + h * HDIM + i;
    float x = X[off];
    float ss = x * x;
#pragma unroll
    for (int o = 16; o; o >>= 1)
        ss += __shfl_xor_sync(0xffffffffu, ss, o);
    __shared__ float sred[4];
    if ((i & 31) == 0) sred[i >> 5] = ss;
    __syncthreads();
    ss = sred[0] + sred[1] + sred[2] + sred[3];
    float rn = rsqrtf(ss * (1.0f / HDIM) + 1e-6f);
    float xn = x * rn * w[i];
    __shared__ float sh[HDIM];
    sh[i] = xn;
    __syncthreads();
    const int f = i & 63;
    float invf = exp2f((float)f * (-13.287712379549449f / 64.0f));
    float ang = (float)t * invf;
    float c, s;
    sincosf(ang, &s, &c);
    float partner = (i < 64) ? -sh[i + 64] : sh[i - 64];
    float out = xn * c + partner * s;
    bf16 hh, ll;
    split2(out, hh, ll);
    H[off] = hh;
    L[off] = ll;
}

// ======== causal flash attention on HMMA (bf16 split, fp32 softmax) ========
// BQ = BKV = 64, HD = 128, 256 threads (8 warps: 4m x 2n).
#define QK_STR 136   // 128 + 8 pad, bf16 units
#define P_STR  72    // 64 + 8 pad
#define OFF_QH 0
#define OFF_QL 8704
#define OFF_KH 17408
#define OFF_KL 26112
#define OFF_VH 34816
#define OFF_VL 43520
#define OFF_PH 52224
#define OFF_PL 56832
#define FLASH_SMEM_BYTES (61440 * 2 + 2 * 128 * 4)   // bf16 region + red buffers
#define SCL 0.1275175f   // (1/sqrt(128)) * log2(e)

__global__ __launch_bounds__(256, 1)
void flash_mma(const bf16* __restrict__ Qh, const bf16* __restrict__ Ql,
               const bf16* __restrict__ Kh, const bf16* __restrict__ Kl,
               const bf16* __restrict__ Vh, const bf16* __restrict__ Vl,
               bf16* __restrict__ Oh, bf16* __restrict__ Ol) {
    extern __shared__ char smraw[];
    bf16* S = (bf16*)smraw;
    float* redmax = (float*)(smraw + 61440 * 2);      // [2][64]
    float* redsum = redmax + 128;                     // [2][64]

    const int qb = blockIdx.x;
    const int pair = blockIdx.y;
    const int b = pair >> 4, h = pair & 15;
    const int tid = threadIdx.x, lane = tid & 31, warp = tid >> 5;
    const int wm = (warp & 3) * 16;         // m rows (same for S and O)
    const int wnS = (warp >> 2) * 32;       // S cols
    const int wnO = (warp >> 2) * 64;       // O cols
    const int wp = warp >> 2;               // warp-pair half
    const int er = lane >> 2, ec = (lane & 3) << 1;
    const int lrA = lane & 15, lcA = (lane >> 4) << 3;
    const int lrB = lane & 7,  sel8 = ((lane >> 3) & 1) << 3;

    const uint32_t sQh = smem_u32(S + OFF_QH), sQl = smem_u32(S + OFF_QL);
    const uint32_t sKh = smem_u32(S + OFF_KH), sKl = smem_u32(S + OFF_KL);
    const uint32_t sVh = smem_u32(S + OFF_VH), sVl = smem_u32(S + OFF_VL);
    const uint32_t sPh = smem_u32(S + OFF_PH), sPl = smem_u32(S + OFF_PL);

    const size_t bT = (size_t)b * TSEQ;
    const int hoff = h * HDIM;

    // ---- load Q tile (64 x 128 hi/lo) ----
#pragma unroll
    for (int i = 0; i < 4; i++) {
        int idx = tid + i * 256;
        int row = idx >> 4, ch = idx & 15;
        size_t g = (bT + qb * 64 + row) * DMODEL + hoff + ch * 8;
        int so = row * QK_STR + ch * 8;
        *(uint4*)(S + OFF_QH + so) = *(const uint4*)(Qh + g);
        *(uint4*)(S + OFF_QL + so) = *(const uint4*)(Ql + g);
    }

    float o[8][4];
#pragma unroll
    for (int i = 0; i < 8; i++)
#pragma unroll
        for (int j = 0; j < 4; j++) o[i][j] = 0.f;
    float m0 = -1e30f, m1 = -1e30f, l0 = 0.f, l1 = 0.f;

    const int rl_lo = wm + er, rl_hi = wm + er + 8;   // local row ids

    for (int kb = 0; kb <= qb; kb++) {
        __syncthreads();   // prior iter's reads done (also Q barrier on kb=0)
        // ---- load K, V tiles ----
#pragma unroll
        for (int i = 0; i < 4; i++) {
            int idx = tid + i * 256;
            int row = idx >> 4, ch = idx & 15;
            size_t g = (bT + kb * 64 + row) * DMODEL + hoff + ch * 8;
            int so = row * QK_STR + ch * 8;
            *(uint4*)(S + OFF_KH + so) = *(const uint4*)(Kh + g);
            *(uint4*)(S + OFF_KL + so) = *(const uint4*)(Kl + g);
            *(uint4*)(S + OFF_VH + so) = *(const uint4*)(Vh + g);
            *(uint4*)(S + OFF_VL + so) = *(const uint4*)(Vl + g);
        }
        __syncthreads();

        // ---- S = Q K^T (3-term split), warp tile 16x32 ----
        float c[4][4];
#pragma unroll
        for (int i = 0; i < 4; i++)
#pragma unroll
            for (int j = 0; j < 4; j++) c[i][j] = 0.f;

#pragma unroll
        for (int ks = 0; ks < 8; ks++) {
            uint32_t ah[4], al[4];
            uint32_t offA = (uint32_t)(((wm + lrA) * QK_STR + ks * 16 + lcA) * 2);
            LDM4(ah, sQh + offA);
            LDM4(al, sQl + offA);
#pragma unroll
            for (int nt = 0; nt < 4; nt++) {
                uint32_t bh[2], bl[2];
                uint32_t offB = (uint32_t)(((wnS + nt * 8 + lrB) * QK_STR + ks * 16 + sel8) * 2);
                LDM2(bh, sKh + offB);
                LDM2(bl, sKl + offB);
                MMA_BF16(c[nt], ah, bh);
                MMA_BF16(c[nt], ah, bl);
                MMA_BF16(c[nt], al, bh);
            }
        }

        // ---- softmax (base-2 domain, scale folded) ----
        const bool diag = (kb == qb);
        const int grow_lo = qb * 64 + rl_lo, grow_hi = qb * 64 + rl_hi;
        float mx0 = -1e30f, mx1 = -1e30f;
#pragma unroll
        for (int nt = 0; nt < 4; nt++) {
            int col = kb * 64 + wnS + nt * 8 + ec;
#pragma unroll
            for (int j = 0; j < 2; j++) {
                float s0 = c[nt][j] * SCL;
                float s1 = c[nt][j + 2] * SCL;
                if (diag) {
                    if (col + j > grow_lo) s0 = -1e30f;
                    if (col + j > grow_hi) s1 = -1e30f;
                }
                c[nt][j] = s0; c[nt][j + 2] = s1;
                mx0 = fmaxf(mx0, s0); mx1 = fmaxf(mx1, s1);
            }
        }
        mx0 = fmaxf(mx0, __shfl_xor_sync(0xffffffffu, mx0, 1));
        mx0 = fmaxf(mx0, __shfl_xor_sync(0xffffffffu, mx0, 2));
        mx1 = fmaxf(mx1, __shfl_xor_sync(0xffffffffu, mx1, 1));
        mx1 = fmaxf(mx1, __shfl_xor_sync(0xffffffffu, mx1, 2));
        if ((lane & 3) == 0) {
            redmax[wp * 64 + rl_lo] = mx0;
            redmax[wp * 64 + rl_hi] = mx1;
        }
        __syncthreads();
        float m0n = fmaxf(m0, fmaxf(redmax[rl_lo], redmax[64 + rl_lo]));
        float m1n = fmaxf(m1, fmaxf(redmax[rl_hi], redmax[64 + rl_hi]));
        float a0 = ex2(m0 - m0n), a1 = ex2(m1 - m1n);
        m0 = m0n; m1 = m1n;

        float sum0 = 0.f, sum1 = 0.f;
#pragma unroll
        for (int nt = 0; nt < 4; nt++) {
            float p0 = ex2(c[nt][0] - m0n), p1 = ex2(c[nt][1] - m0n);
            float p2 = ex2(c[nt][2] - m1n), p3 = ex2(c[nt][3] - m1n);
            sum0 += p0 + p1; sum1 += p2 + p3;
            bf16 h0, q0, h1, q1, h2, q2, h3, q3;
            split2(p0, h0, q0); split2(p1, h1, q1);
            split2(p2, h2, q2); split2(p3, h3, q3);
            int cbase = wnS + nt * 8 + ec;
            *(__nv_bfloat162*)(S + OFF_PH + rl_lo * P_STR + cbase) = __nv_bfloat162(h0, h1);
            *(__nv_bfloat162*)(S + OFF_PH + rl_hi * P_STR + cbase) = __nv_bfloat162(h2, h3);
            *(__nv_bfloat162*)(S + OFF_PL + rl_lo * P_STR + cbase) = __nv_bfloat162(q0, q1);
            *(__nv_bfloat162*)(S + OFF_PL + rl_hi * P_STR + cbase) = __nv_bfloat162(q2, q3);
        }
        sum0 += __shfl_xor_sync(0xffffffffu, sum0, 1);
        sum0 += __shfl_xor_sync(0xffffffffu, sum0, 2);
        sum1 += __shfl_xor_sync(0xffffffffu, sum1, 1);
        sum1 += __shfl_xor_sync(0xffffffffu, sum1, 2);
        if ((lane & 3) == 0) {
            redsum[wp * 64 + rl_lo] = sum0;
            redsum[wp * 64 + rl_hi] = sum1;
        }
        // rescale O accumulators
#pragma unroll
        for (int nt = 0; nt < 8; nt++) {
            o[nt][0] *= a0; o[nt][1] *= a0;
            o[nt][2] *= a1; o[nt][3] *= a1;
        }
        __syncthreads();
        l0 = l0 * a0 + redsum[rl_lo] + redsum[64 + rl_lo];
        l1 = l1 * a1 + redsum[rl_hi] + redsum[64 + rl_hi];

        // ---- O += P V (3-term split), warp tile 16x64 ----
#pragma unroll
        for (int ks = 0; ks < 4; ks++) {
            uint32_t ph[4], pl[4];
            uint32_t offP = (uint32_t)(((wm + lrA) * P_STR + ks * 16 + lcA) * 2);
            LDM4(ph, sPh + offP);
            LDM4(pl, sPl + offP);
#pragma unroll
            for (int nt = 0; nt < 8; nt++) {
                uint32_t vh[2], vl[2];
                uint32_t offV = (uint32_t)(((ks * 16 + lrB + sel8) * QK_STR + wnO + nt * 8) * 2);
                LDM2T(vh, sVh + offV);
                LDM2T(vl, sVl + offV);
                MMA_BF16(o[nt], ph, vh);
                MMA_BF16(o[nt], pl, vh);
                MMA_BF16(o[nt], ph, vl);
            }
        }
    }

    // ---- normalize + write hi/lo O ----
    float inv0 = 1.f / l0, inv1 = 1.f / l1;
    size_t tok_lo = (bT + qb * 64 + rl_lo) * DMODEL + hoff;
    size_t tok_hi = (bT + qb * 64 + rl_hi) * DMODEL + hoff;
#pragma unroll
    for (int nt = 0; nt < 8; nt++) {
        int col = wnO + nt * 8 + ec;
        float v0 = o[nt][0] * inv0, v1 = o[nt][1] * inv0;
        float v2 = o[nt][2] * inv1, v3 = o[nt][3] * inv1;
        bf16 h0, q0, h1, q1, h2, q2, h3, q3;
        split2(v0, h0, q0); split2(v1, h1, q1);
        split2(v2, h2, q2); split2(v3, h3, q3);
        *(__nv_bfloat162*)(Oh + tok_lo + col) = __nv_bfloat162(h0, h1);
        *(__nv_bfloat162*)(Oh + tok_hi + col) = __nv_bfloat162(h2, h3);
        *(__nv_bfloat162*)(Ol + tok_lo + col) = __nv_bfloat162(q0, q1);
        *(__nv_bfloat162*)(Ol + tok_hi + col) = __nv_bfloat162(q2, q3);
    }
}

// ---------------- launch ----------------------------------------------------
static inline void conv(const float* in, bf16* h, bf16* l, int n) {
    int n4 = n / 4;
    conv_hilo<<<(n4 + 255) / 256, 256>>>(in, h, l, n4);
}

extern "C" void kernel_launch(void* const* d_in, const int* in_sizes, int n_in,
                              void* d_out, int out_size) {
    const float* x      = (const float*)d_in[0];
    const float* q_a_w  = (const float*)d_in[2];
    const float* q_b_w  = (const float*)d_in[3];
    const float* kv_a_w = (const float*)d_in[4];
    const float* k_b_w  = (const float*)d_in[5];
    const float* v_b_w  = (const float*)d_in[6];
    const float* o_w    = (const float*)d_in[7];
    const float* q_nw   = (const float*)d_in[8];
    const float* k_nw   = (const float*)d_in[9];

    float *q, *k;
    bf16 *xh, *xl, *qlh, *qll, *kvh, *kvl;
    bf16 *qh, *ql, *kh, *kl, *vh, *vl, *aoh, *aol;
    bf16 *wqah, *wqal, *wqbh, *wqbl, *wkvh, *wkvl, *wkbh, *wkbl, *wvbh, *wvbl, *owh, *owl;
    cudaGetSymbolAddress((void**)&q, g_q);     cudaGetSymbolAddress((void**)&k, g_k);
    cudaGetSymbolAddress((void**)&xh, g_xh);   cudaGetSymbolAddress((void**)&xl, g_xl);
    cudaGetSymbolAddress((void**)&qlh, g_qlh); cudaGetSymbolAddress((void**)&qll, g_qll);
    cudaGetSymbolAddress((void**)&kvh, g_kvh); cudaGetSymbolAddress((void**)&kvl, g_kvl);
    cudaGetSymbolAddress((void**)&qh, g_qh);   cudaGetSymbolAddress((void**)&ql, g_ql);
    cudaGetSymbolAddress((void**)&kh, g_kh);   cudaGetSymbolAddress((void**)&kl, g_kl);
    cudaGetSymbolAddress((void**)&vh, g_vh);   cudaGetSymbolAddress((void**)&vl, g_vl);
    cudaGetSymbolAddress((void**)&aoh, g_aoh); cudaGetSymbolAddress((void**)&aol, g_aol);
    cudaGetSymbolAddress((void**)&wqah, g_wqah); cudaGetSymbolAddress((void**)&wqal, g_wqal);
    cudaGetSymbolAddress((void**)&wqbh, g_wqbh); cudaGetSymbolAddress((void**)&wqbl, g_wqbl);
    cudaGetSymbolAddress((void**)&wkvh, g_wkvh); cudaGetSymbolAddress((void**)&wkvl, g_wkvl);
    cudaGetSymbolAddress((void**)&wkbh, g_wkbh); cudaGetSymbolAddress((void**)&wkbl, g_wkbl);
    cudaGetSymbolAddress((void**)&wvbh, g_wvbh); cudaGetSymbolAddress((void**)&wvbl, g_wvbl);
    cudaGetSymbolAddress((void**)&owh, g_owh);   cudaGetSymbolAddress((void**)&owl, g_owl);

    cudaFuncSetAttribute(flash_mma, cudaFuncAttributeMaxDynamicSharedMemorySize,
                         FLASH_SMEM_BYTES);

    // fp32 -> bf16 hi/lo conversions (inputs + weights)
    conv(x, xh, xl, TOKENS * DMODEL);
    conv(q_a_w, wqah, wqal, QLATD * DMODEL);
    conv(q_b_w, wqbh, wqbl, DMODEL * QLATD);
    conv(kv_a_w, wkvh, wkvl, KVLATD * DMODEL);
    conv(k_b_w, wkbh, wkbl, DMODEL * KVLATD);
    conv(v_b_w, wvbh, wvbl, DMODEL * KVLATD);
    conv(o_w, owh, owl, DMODEL * DMODEL);

    // projections on HMMA (3-term bf16 split)
    gemm_mma<<<dim3(QLATD / 128, TOKENS / 128), 256>>>(
        xh, xl, wqah, wqal, nullptr, qlh, qll, TOKENS, QLATD, DMODEL);
    gemm_mma<<<dim3(DMODEL / 128, TOKENS / 128), 256>>>(
        qlh, qll, wqbh, wqbl, q, nullptr, nullptr, TOKENS, DMODEL, QLATD);
    gemm_mma<<<dim3(KVLATD / 128, TOKENS / 128), 256>>>(
        xh, xl, wkvh, wkvl, nullptr, kvh, kvl, TOKENS, KVLATD, DMODEL);
    gemm_mma<<<dim3(DMODEL / 128, TOKENS / 128), 256>>>(
        kvh, kvl, wkbh, wkbl, k, nullptr, nullptr, TOKENS, DMODEL, KVLATD);
    gemm_mma<<<dim3(DMODEL / 128, TOKENS / 128), 256>>>(
        kvh, kvl, wvbh, wvbl, nullptr, vh, vl, TOKENS, DMODEL, KVLATD);

    // per-head RMSNorm + RoPE -> bf16 hi/lo
    norm_rope_kernel<<<TOKENS * NHEADS, 128>>>(q, q_nw, qh, ql);
    norm_rope_kernel<<<TOKENS * NHEADS, 128>>>(k, k_nw, kh, kl);

    // causal flash attention on HMMA
    flash_mma<<<dim3(TSEQ / 64, 2 * NHEADS), 256, FLASH_SMEM_BYTES>>>(
        qh, ql, kh, kl, vh, vl, aoh, aol);

    // output projection -> fp32 d_out
    gemm_mma<<<dim3(DMODEL / 128, TOKENS / 128), 256>>>(
        aoh, aol, owh, owl, (float*)d_out, nullptr, nullptr, TOKENS, DMODEL, DMODEL);
}

// round 5
// speedup vs baseline: 2.6316x; 1.3250x over previous
#include <cuda_runtime.h>
#include <cuda_bf16.h>
#include <math.h>
#include <cstdint>

#define TOKENS 4096   // B*T
#define DMODEL 2048   // NH*HD
#define TSEQ   2048
#define NHEADS 16
#define HDIM   128
#define QLATD  1024
#define KVLATD 512

typedef __nv_bfloat16 bf16;

// ---------------- scratch (device globals; no allocation allowed) ----------
__device__ float g_q  [TOKENS * DMODEL];
__device__ float g_k  [TOKENS * DMODEL];
__device__ bf16 g_xh [TOKENS * DMODEL],  g_xl [TOKENS * DMODEL];
__device__ bf16 g_qlh[TOKENS * QLATD],   g_qll[TOKENS * QLATD];
__device__ bf16 g_kvh[TOKENS * KVLATD],  g_kvl[TOKENS * KVLATD];
__device__ bf16 g_qh [TOKENS * DMODEL],  g_ql [TOKENS * DMODEL];
__device__ bf16 g_kh [TOKENS * DMODEL],  g_kl [TOKENS * DMODEL];
__device__ bf16 g_vh [TOKENS * DMODEL],  g_vl [TOKENS * DMODEL];
__device__ bf16 g_aoh[TOKENS * DMODEL],  g_aol[TOKENS * DMODEL];
__device__ bf16 g_wqah[QLATD * DMODEL],  g_wqal[QLATD * DMODEL];
__device__ bf16 g_wqbh[DMODEL * QLATD],  g_wqbl[DMODEL * QLATD];
__device__ bf16 g_wkvh[KVLATD * DMODEL], g_wkvl[KVLATD * DMODEL];
__device__ bf16 g_wkbh[DMODEL * KVLATD], g_wkbl[DMODEL * KVLATD];
__device__ bf16 g_wvbh[DMODEL * KVLATD], g_wvbl[DMODEL * KVLATD];
__device__ bf16 g_owh [DMODEL * DMODEL], g_owl [DMODEL * DMODEL];

// ================= helpers (baseline PTX, no "a"-features) =================
__device__ __forceinline__ uint32_t smem_u32(const void* p) {
    uint32_t a;
    asm("{ .reg .u64 t; cvta.to.shared.u64 t, %1; cvt.u32.u64 %0, t; }"
        : "=r"(a) : "l"(p));
    return a;
}
__device__ __forceinline__ float ex2(float x) {
    float y;
    asm("ex2.approx.ftz.f32 %0, %1;" : "=f"(y) : "f"(x));
    return y;
}

#define CP_ASYNC16(sa, gp) \
    asm volatile("cp.async.cg.shared.global [%0], [%1], 16;" :: "r"(sa), "l"(gp))
#define CP_COMMIT() asm volatile("cp.async.commit_group;" ::: "memory")
#define CP_WAIT0()  asm volatile("cp.async.wait_group 0;" ::: "memory")
#define CP_WAIT1()  asm volatile("cp.async.wait_group 1;" ::: "memory")

#define LDM4(r, addr) \
    asm volatile("ldmatrix.sync.aligned.m8n8.x4.shared.b16 {%0,%1,%2,%3}, [%4];" \
                 : "=r"((r)[0]), "=r"((r)[1]), "=r"((r)[2]), "=r"((r)[3]) : "r"(addr))
#define LDM4T(r, addr) \
    asm volatile("ldmatrix.sync.aligned.m8n8.x4.trans.shared.b16 {%0,%1,%2,%3}, [%4];" \
                 : "=r"((r)[0]), "=r"((r)[1]), "=r"((r)[2]), "=r"((r)[3]) : "r"(addr))
#define MMA_BF16(d, a, b) \
    asm volatile("mma.sync.aligned.m16n8k16.row.col.f32.bf16.bf16.f32 " \
                 "{%0,%1,%2,%3}, {%4,%5,%6,%7}, {%8,%9}, {%0,%1,%2,%3};" \
                 : "+f"((d)[0]), "+f"((d)[1]), "+f"((d)[2]), "+f"((d)[3]) \
                 : "r"((a)[0]), "r"((a)[1]), "r"((a)[2]), "r"((a)[3]), \
                   "r"((b)[0]), "r"((b)[1]))

__device__ __forceinline__ void split2(float v, bf16& h, bf16& l) {
    h = __float2bfloat16_rn(v);
    l = __float2bfloat16_rn(v - __bfloat162float(h));
}

// ============= tensor-core GEMM: C[M,N] = (Ah+Al)[M,K] * (Bh+Bl)[N,K]^T ====
// 128x128 tile, BK=32, cp.async 2-stage double buffer, 8 warps (2m x 4n).
#define SSTR 40
#define G_ARR  10240                       // bytes per array (128*40*2)
#define G_STG  (4 * G_ARR)                 // bytes per stage
#define GEMM_SMEM_BYTES (2 * G_STG)        // 81920

__global__ __launch_bounds__(256)
void gemm_mma(const bf16* __restrict__ Ah, const bf16* __restrict__ Al,
              const bf16* __restrict__ Bh, const bf16* __restrict__ Bl,
              float* __restrict__ Cf, bf16* __restrict__ Ch,
              bf16* __restrict__ Cl, int M, int N, int K) {
    extern __shared__ bf16 sg[];
    const uint32_t sb = smem_u32(sg);

    const int tid = threadIdx.x, lane = tid & 31, warp = tid >> 5;
    const int wm = (warp & 1) * 64, wn = (warp >> 1) * 32;
    const int bm = blockIdx.y * 128, bn = blockIdx.x * 128;

    const int lrA = lane & 15, lcA = (lane >> 4) << 3;
    const int l7 = lane & 7;
    const int k8 = ((lane >> 3) & 1) << 3;
    const int n8 = ((lane >> 4) & 1) << 3;

    float c[4][4][4];
#pragma unroll
    for (int i = 0; i < 4; i++)
#pragma unroll
        for (int j = 0; j < 4; j++)
#pragma unroll
            for (int k = 0; k < 4; k++) c[i][j][k] = 0.f;

    auto load_stage = [&](int kt, int s) {
        uint32_t so = sb + (uint32_t)s * G_STG;
#pragma unroll
        for (int i = 0; i < 2; i++) {
            int idx = tid + i * 256;                 // 512 chunks per array
            int row = idx >> 2, cc = idx & 3;
            size_t gA = (size_t)(bm + row) * K + kt + cc * 8;
            size_t gB = (size_t)(bn + row) * K + kt + cc * 8;
            uint32_t off = (uint32_t)(row * (SSTR * 2) + cc * 16);
            CP_ASYNC16(so + off,             Ah + gA);
            CP_ASYNC16(so + G_ARR + off,     Al + gA);
            CP_ASYNC16(so + 2 * G_ARR + off, Bh + gB);
            CP_ASYNC16(so + 3 * G_ARR + off, Bl + gB);
        }
    };

    const int nkt = K >> 5;
    load_stage(0, 0);
    CP_COMMIT();

    for (int kt = 0; kt < nkt; kt++) {
        if (kt + 1 < nkt) {
            load_stage((kt + 1) << 5, (kt + 1) & 1);
            CP_COMMIT();
            CP_WAIT1();
        } else {
            CP_WAIT0();
        }
        __syncthreads();

        const uint32_t aAh = sb + (uint32_t)(kt & 1) * G_STG;
        const uint32_t aAl = aAh + G_ARR;
        const uint32_t aBh = aAh + 2 * G_ARR;
        const uint32_t aBl = aAh + 3 * G_ARR;

#pragma unroll
        for (int ks = 0; ks < 32; ks += 16) {
            uint32_t bh[4][2], bl[4][2], t[4];
#pragma unroll
            for (int p = 0; p < 2; p++) {
                uint32_t off = (uint32_t)(((wn + p * 16 + n8 + l7) * SSTR + ks + k8) * 2);
                LDM4(t, aBh + off);
                bh[2 * p][0] = t[0]; bh[2 * p][1] = t[1];
                bh[2 * p + 1][0] = t[2]; bh[2 * p + 1][1] = t[3];
                LDM4(t, aBl + off);
                bl[2 * p][0] = t[0]; bl[2 * p][1] = t[1];
                bl[2 * p + 1][0] = t[2]; bl[2 * p + 1][1] = t[3];
            }
#pragma unroll
            for (int mt = 0; mt < 4; mt++) {
                uint32_t off = (uint32_t)(((wm + mt * 16 + lrA) * SSTR + ks + lcA) * 2);
                uint32_t ah[4], al[4];
                LDM4(ah, aAh + off);
                LDM4(al, aAl + off);
#pragma unroll
                for (int nt = 0; nt < 4; nt++) {
                    MMA_BF16(c[mt][nt], ah, bh[nt]);
                    MMA_BF16(c[mt][nt], ah, bl[nt]);
                    MMA_BF16(c[mt][nt], al, bh[nt]);
                }
            }
        }
        __syncthreads();
    }

    const int er = lane >> 2, ec = (lane & 3) << 1;
#pragma unroll
    for (int mt = 0; mt < 4; mt++) {
#pragma unroll
        for (int nt = 0; nt < 4; nt++) {
            size_t r0 = (size_t)(bm + wm + mt * 16 + er);
            int c0 = bn + wn + nt * 8 + ec;
            float v0 = c[mt][nt][0], v1 = c[mt][nt][1];
            float v2 = c[mt][nt][2], v3 = c[mt][nt][3];
            if (Cf) {
                *(float2*)(Cf + r0 * N + c0)       = make_float2(v0, v1);
                *(float2*)(Cf + (r0 + 8) * N + c0) = make_float2(v2, v3);
            }
            if (Ch) {
                bf16 h0, l0, h1, l1, h2, l2, h3, l3;
                split2(v0, h0, l0); split2(v1, h1, l1);
                split2(v2, h2, l2); split2(v3, h3, l3);
                *(__nv_bfloat162*)(Ch + r0 * N + c0)       = __nv_bfloat162(h0, h1);
                *(__nv_bfloat162*)(Ch + (r0 + 8) * N + c0) = __nv_bfloat162(h2, h3);
                *(__nv_bfloat162*)(Cl + r0 * N + c0)       = __nv_bfloat162(l0, l1);
                *(__nv_bfloat162*)(Cl + (r0 + 8) * N + c0) = __nv_bfloat162(l2, l3);
            }
        }
    }
}

// ---------------- fp32 -> (bf16 hi, bf16 lo) ------------------------------
__global__ __launch_bounds__(256)
void conv_hilo(const float* __restrict__ in, bf16* __restrict__ hi,
               bf16* __restrict__ lo, int n4) {
    int i = blockIdx.x * 256 + threadIdx.x;
    if (i >= n4) return;
    float4 x = ((const float4*)in)[i];
    float v[4] = {x.x, x.y, x.z, x.w};
    bf16 h[4], l[4];
#pragma unroll
    for (int j = 0; j < 4; j++) split2(v[j], h[j], l[j]);
    ((__nv_bfloat162*)hi)[i * 2]     = __nv_bfloat162(h[0], h[1]);
    ((__nv_bfloat162*)hi)[i * 2 + 1] = __nv_bfloat162(h[2], h[3]);
    ((__nv_bfloat162*)lo)[i * 2]     = __nv_bfloat162(l[0], l[1]);
    ((__nv_bfloat162*)lo)[i * 2 + 1] = __nv_bfloat162(l[2], l[3]);
}

// -------- fused per-head RMSNorm + RoPE, emitting bf16 hi/lo ---------------
__global__ __launch_bounds__(128)
void norm_rope_kernel(const float* __restrict__ X, const float* __restrict__ w,
                      bf16* __restrict__ H, bf16* __restrict__ L) {
    const int blk = blockIdx.x;
    const int token = blk >> 4, h = blk & 15;
    const int t = token & (TSEQ - 1);
    const int i = threadIdx.x;
    const size_t off = (size_t)token * DMODEL + h * HDIM + i;
    float x = X[off];
    float ss = x * x;
#pragma unroll
    for (int o = 16; o; o >>= 1)
        ss += __shfl_xor_sync(0xffffffffu, ss, o);
    __shared__ float sred[4];
    if ((i & 31) == 0) sred[i >> 5] = ss;
    __syncthreads();
    ss = sred[0] + sred[1] + sred[2] + sred[3];
    float rn = rsqrtf(ss * (1.0f / HDIM) + 1e-6f);
    float xn = x * rn * w[i];
    __shared__ float sh[HDIM];
    sh[i] = xn;
    __syncthreads();
    const int f = i & 63;
    float invf = exp2f((float)f * (-13.287712379549449f / 64.0f));
    float ang = (float)t * invf;
    float c, s;
    sincosf(ang, &s, &c);
    float partner = (i < 64) ? -sh[i + 64] : sh[i - 64];
    float out = xn * c + partner * s;
    bf16 hh, ll;
    split2(out, hh, ll);
    H[off] = hh;
    L[off] = ll;
}

// ======== causal flash attention on HMMA (bf16 split, fp32 softmax) ========
// BQ = BKV = 64, 256 threads (8 warps: 4m x 2n), cp.async K/V double buffer.
#define QK_STR 136   // bf16 units (272 B rows)
#define P_STR  72    // bf16 units (144 B rows)
#define F_QH 0
#define F_QL 17408
#define F_KV0 34816          // stage base; stage stride:
#define F_KVS 69632
#define F_KH 0
#define F_KL 17408
#define F_VH 34816
#define F_VL 52224
#define F_PH 174080
#define F_PL 183296
#define F_RED 192512
#define FLASH_SMEM_BYTES 193536
#define SCL 0.1275175f   // (1/sqrt(128)) * log2(e)

__global__ __launch_bounds__(256, 1)
void flash_mma(const bf16* __restrict__ Qh, const bf16* __restrict__ Ql,
               const bf16* __restrict__ Kh, const bf16* __restrict__ Kl,
               const bf16* __restrict__ Vh, const bf16* __restrict__ Vl,
               bf16* __restrict__ Oh, bf16* __restrict__ Ol) {
    extern __shared__ char smraw[];
    const uint32_t sb = smem_u32(smraw);
    float* redmax = (float*)(smraw + F_RED);          // [2][64]
    float* redsum = redmax + 128;                     // [2][64]

    const int qb = blockIdx.x;
    const int pair = blockIdx.y;
    const int b = pair >> 4, h = pair & 15;
    const int tid = threadIdx.x, lane = tid & 31, warp = tid >> 5;
    const int wm = (warp & 3) * 16;
    const int wnS = (warp >> 2) * 32;
    const int wnO = (warp >> 2) * 64;
    const int wp = warp >> 2;
    const int er = lane >> 2, ec = (lane & 3) << 1;
    const int lrA = lane & 15, lcA = (lane >> 4) << 3;
    const int l7 = lane & 7;
    const int k8 = ((lane >> 3) & 1) << 3;
    const int n8 = ((lane >> 4) & 1) << 3;

    const size_t bT = (size_t)b * TSEQ;
    const int hoff = h * HDIM;

    // ---- async load Q tile + first K/V stage ----
#pragma unroll
    for (int i = 0; i < 4; i++) {
        int idx = tid + i * 256;
        int row = idx >> 4, ch = idx & 15;
        size_t g = (bT + qb * 64 + row) * DMODEL + hoff + ch * 8;
        uint32_t off = (uint32_t)(row * (QK_STR * 2) + ch * 16);
        CP_ASYNC16(sb + F_QH + off, Qh + g);
        CP_ASYNC16(sb + F_QL + off, Ql + g);
    }
    auto load_kv = [&](int kb, int s) {
        uint32_t so = sb + F_KV0 + (uint32_t)s * F_KVS;
#pragma unroll
        for (int i = 0; i < 4; i++) {
            int idx = tid + i * 256;
            int row = idx >> 4, ch = idx & 15;
            size_t g = (bT + kb * 64 + row) * DMODEL + hoff + ch * 8;
            uint32_t off = (uint32_t)(row * (QK_STR * 2) + ch * 16);
            CP_ASYNC16(so + F_KH + off, Kh + g);
            CP_ASYNC16(so + F_KL + off, Kl + g);
            CP_ASYNC16(so + F_VH + off, Vh + g);
            CP_ASYNC16(so + F_VL + off, Vl + g);
        }
    };
    load_kv(0, 0);
    CP_COMMIT();

    float o[8][4];
#pragma unroll
    for (int i = 0; i < 8; i++)
#pragma unroll
        for (int j = 0; j < 4; j++) o[i][j] = 0.f;
    float m0 = -1e30f, m1 = -1e30f, l0 = 0.f, l1 = 0.f;

    const int rl_lo = wm + er, rl_hi = wm + er + 8;

    for (int kb = 0; kb <= qb; kb++) {
        if (kb < qb) {
            load_kv(kb + 1, (kb + 1) & 1);
            CP_COMMIT();
            CP_WAIT1();
        } else {
            CP_WAIT0();
        }
        __syncthreads();

        const uint32_t sKV = sb + F_KV0 + (uint32_t)(kb & 1) * F_KVS;
        const uint32_t sKh = sKV + F_KH, sKl = sKV + F_KL;
        const uint32_t sVh = sKV + F_VH, sVl = sKV + F_VL;

        // ---- S = Q K^T (3-term split), warp tile 16x32 ----
        float c[4][4];
#pragma unroll
        for (int i = 0; i < 4; i++)
#pragma unroll
            for (int j = 0; j < 4; j++) c[i][j] = 0.f;

#pragma unroll
        for (int ks = 0; ks < 8; ks++) {
            uint32_t ah[4], al[4];
            uint32_t offA = (uint32_t)(((wm + lrA) * QK_STR + ks * 16 + lcA) * 2);
            LDM4(ah, sb + F_QH + offA);
            LDM4(al, sb + F_QL + offA);
            uint32_t bh[4][2], bl[4][2], t[4];
#pragma unroll
            for (int p = 0; p < 2; p++) {
                uint32_t offB = (uint32_t)(((wnS + p * 16 + n8 + l7) * QK_STR + ks * 16 + k8) * 2);
                LDM4(t, sKh + offB);
                bh[2 * p][0] = t[0]; bh[2 * p][1] = t[1];
                bh[2 * p + 1][0] = t[2]; bh[2 * p + 1][1] = t[3];
                LDM4(t, sKl + offB);
                bl[2 * p][0] = t[0]; bl[2 * p][1] = t[1];
                bl[2 * p + 1][0] = t[2]; bl[2 * p + 1][1] = t[3];
            }
#pragma unroll
            for (int nt = 0; nt < 4; nt++) {
                MMA_BF16(c[nt], ah, bh[nt]);
                MMA_BF16(c[nt], ah, bl[nt]);
                MMA_BF16(c[nt], al, bh[nt]);
            }
        }

        // ---- softmax (base-2 domain) ----
        const bool diag = (kb == qb);
        const int grow_lo = qb * 64 + rl_lo, grow_hi = qb * 64 + rl_hi;
        float mx0 = -1e30f, mx1 = -1e30f;
#pragma unroll
        for (int nt = 0; nt < 4; nt++) {
            int col = kb * 64 + wnS + nt * 8 + ec;
#pragma unroll
            for (int j = 0; j < 2; j++) {
                float s0 = c[nt][j] * SCL;
                float s1 = c[nt][j + 2] * SCL;
                if (diag) {
                    if (col + j > grow_lo) s0 = -1e30f;
                    if (col + j > grow_hi) s1 = -1e30f;
                }
                c[nt][j] = s0; c[nt][j + 2] = s1;
                mx0 = fmaxf(mx0, s0); mx1 = fmaxf(mx1, s1);
            }
        }
        mx0 = fmaxf(mx0, __shfl_xor_sync(0xffffffffu, mx0, 1));
        mx0 = fmaxf(mx0, __shfl_xor_sync(0xffffffffu, mx0, 2));
        mx1 = fmaxf(mx1, __shfl_xor_sync(0xffffffffu, mx1, 1));
        mx1 = fmaxf(mx1, __shfl_xor_sync(0xffffffffu, mx1, 2));
        if ((lane & 3) == 0) {
            redmax[wp * 64 + rl_lo] = mx0;
            redmax[wp * 64 + rl_hi] = mx1;
        }
        __syncthreads();
        float m0n = fmaxf(m0, fmaxf(redmax[rl_lo], redmax[64 + rl_lo]));
        float m1n = fmaxf(m1, fmaxf(redmax[rl_hi], redmax[64 + rl_hi]));
        float a0 = ex2(m0 - m0n), a1 = ex2(m1 - m1n);
        m0 = m0n; m1 = m1n;

        bf16* S = (bf16*)smraw;
        float sum0 = 0.f, sum1 = 0.f;
#pragma unroll
        for (int nt = 0; nt < 4; nt++) {
            float p0 = ex2(c[nt][0] - m0n), p1 = ex2(c[nt][1] - m0n);
            float p2 = ex2(c[nt][2] - m1n), p3 = ex2(c[nt][3] - m1n);
            sum0 += p0 + p1; sum1 += p2 + p3;
            bf16 h0, q0, h1, q1, h2, q2, h3, q3;
            split2(p0, h0, q0); split2(p1, h1, q1);
            split2(p2, h2, q2); split2(p3, h3, q3);
            int cbase = wnS + nt * 8 + ec;
            *(__nv_bfloat162*)(S + (F_PH / 2) + rl_lo * P_STR + cbase) = __nv_bfloat162(h0, h1);
            *(__nv_bfloat162*)(S + (F_PH / 2) + rl_hi * P_STR + cbase) = __nv_bfloat162(h2, h3);
            *(__nv_bfloat162*)(S + (F_PL / 2) + rl_lo * P_STR + cbase) = __nv_bfloat162(q0, q1);
            *(__nv_bfloat162*)(S + (F_PL / 2) + rl_hi * P_STR + cbase) = __nv_bfloat162(q2, q3);
        }
        sum0 += __shfl_xor_sync(0xffffffffu, sum0, 1);
        sum0 += __shfl_xor_sync(0xffffffffu, sum0, 2);
        sum1 += __shfl_xor_sync(0xffffffffu, sum1, 1);
        sum1 += __shfl_xor_sync(0xffffffffu, sum1, 2);
        if ((lane & 3) == 0) {
            redsum[wp * 64 + rl_lo] = sum0;
            redsum[wp * 64 + rl_hi] = sum1;
        }
#pragma unroll
        for (int nt = 0; nt < 8; nt++) {
            o[nt][0] *= a0; o[nt][1] *= a0;
            o[nt][2] *= a1; o[nt][3] *= a1;
        }
        __syncthreads();
        l0 = l0 * a0 + redsum[rl_lo] + redsum[64 + rl_lo];
        l1 = l1 * a1 + redsum[rl_hi] + redsum[64 + rl_hi];

        // ---- O += P V (3-term split), warp tile 16x64 ----
#pragma unroll
        for (int ks = 0; ks < 4; ks++) {
            uint32_t ph[4], pl[4];
            uint32_t offP = (uint32_t)(((wm + lrA) * P_STR + ks * 16 + lcA) * 2);
            LDM4(ph, sb + F_PH + offP);
            LDM4(pl, sb + F_PL + offP);
#pragma unroll
            for (int p = 0; p < 4; p++) {
                uint32_t vh[4], vl[4];
                uint32_t offV = (uint32_t)(((ks * 16 + l7 + k8) * QK_STR + wnO + p * 16 + n8) * 2);
                LDM4T(vh, sVh + offV);
                LDM4T(vl, sVl + offV);
                uint32_t vh0[2] = {vh[0], vh[1]}, vh1[2] = {vh[2], vh[3]};
                uint32_t vl0[2] = {vl[0], vl[1]}, vl1[2] = {vl[2], vl[3]};
                MMA_BF16(o[2 * p], ph, vh0);
                MMA_BF16(o[2 * p], pl, vh0);
                MMA_BF16(o[2 * p], ph, vl0);
                MMA_BF16(o[2 * p + 1], ph, vh1);
                MMA_BF16(o[2 * p + 1], pl, vh1);
                MMA_BF16(o[2 * p + 1], ph, vl1);
            }
        }
        __syncthreads();   // protect stage buffer + P before next iteration
    }

    // ---- normalize + write hi/lo O ----
    float inv0 = 1.f / l0, inv1 = 1.f / l1;
    size_t tok_lo = (bT + qb * 64 + rl_lo) * DMODEL + hoff;
    size_t tok_hi = (bT + qb * 64 + rl_hi) * DMODEL + hoff;
#pragma unroll
    for (int nt = 0; nt < 8; nt++) {
        int col = wnO + nt * 8 + ec;
        float v0 = o[nt][0] * inv0, v1 = o[nt][1] * inv0;
        float v2 = o[nt][2] * inv1, v3 = o[nt][3] * inv1;
        bf16 h0, q0, h1, q1, h2, q2, h3, q3;
        split2(v0, h0, q0); split2(v1, h1, q1);
        split2(v2, h2, q2); split2(v3, h3, q3);
        *(__nv_bfloat162*)(Oh + tok_lo + col) = __nv_bfloat162(h0, h1);
        *(__nv_bfloat162*)(Oh + tok_hi + col) = __nv_bfloat162(h2, h3);
        *(__nv_bfloat162*)(Ol + tok_lo + col) = __nv_bfloat162(q0, q1);
        *(__nv_bfloat162*)(Ol + tok_hi + col) = __nv_bfloat162(q2, q3);
    }
}

// ---------------- launch ----------------------------------------------------
static inline void conv(const float* in, bf16* h, bf16* l, int n) {
    int n4 = n / 4;
    conv_hilo<<<(n4 + 255) / 256, 256>>>(in, h, l, n4);
}

extern "C" void kernel_launch(void* const* d_in, const int* in_sizes, int n_in,
                              void* d_out, int out_size) {
    const float* x      = (const float*)d_in[0];
    const float* q_a_w  = (const float*)d_in[2];
    const float* q_b_w  = (const float*)d_in[3];
    const float* kv_a_w = (const float*)d_in[4];
    const float* k_b_w  = (const float*)d_in[5];
    const float* v_b_w  = (const float*)d_in[6];
    const float* o_w    = (const float*)d_in[7];
    const float* q_nw   = (const float*)d_in[8];
    const float* k_nw   = (const float*)d_in[9];

    float *q, *k;
    bf16 *xh, *xl, *qlh, *qll, *kvh, *kvl;
    bf16 *qh, *ql, *kh, *kl, *vh, *vl, *aoh, *aol;
    bf16 *wqah, *wqal, *wqbh, *wqbl, *wkvh, *wkvl, *wkbh, *wkbl, *wvbh, *wvbl, *owh, *owl;
    cudaGetSymbolAddress((void**)&q, g_q);     cudaGetSymbolAddress((void**)&k, g_k);
    cudaGetSymbolAddress((void**)&xh, g_xh);   cudaGetSymbolAddress((void**)&xl, g_xl);
    cudaGetSymbolAddress((void**)&qlh, g_qlh); cudaGetSymbolAddress((void**)&qll, g_qll);
    cudaGetSymbolAddress((void**)&kvh, g_kvh); cudaGetSymbolAddress((void**)&kvl, g_kvl);
    cudaGetSymbolAddress((void**)&qh, g_qh);   cudaGetSymbolAddress((void**)&ql, g_ql);
    cudaGetSymbolAddress((void**)&kh, g_kh);   cudaGetSymbolAddress((void**)&kl, g_kl);
    cudaGetSymbolAddress((void**)&vh, g_vh);   cudaGetSymbolAddress((void**)&vl, g_vl);
    cudaGetSymbolAddress((void**)&aoh, g_aoh); cudaGetSymbolAddress((void**)&aol, g_aol);
    cudaGetSymbolAddress((void**)&wqah, g_wqah); cudaGetSymbolAddress((void**)&wqal, g_wqal);
    cudaGetSymbolAddress((void**)&wqbh, g_wqbh); cudaGetSymbolAddress((void**)&wqbl, g_wqbl);
    cudaGetSymbolAddress((void**)&wkvh, g_wkvh); cudaGetSymbolAddress((void**)&wkvl, g_wkvl);
    cudaGetSymbolAddress((void**)&wkbh, g_wkbh); cudaGetSymbolAddress((void**)&wkbl, g_wkbl);
    cudaGetSymbolAddress((void**)&wvbh, g_wvbh); cudaGetSymbolAddress((void**)&wvbl, g_wvbl);
    cudaGetSymbolAddress((void**)&owh, g_owh);   cudaGetSymbolAddress((void**)&owl, g_owl);

    cudaFuncSetAttribute(gemm_mma, cudaFuncAttributeMaxDynamicSharedMemorySize,
                         GEMM_SMEM_BYTES);
    cudaFuncSetAttribute(flash_mma, cudaFuncAttributeMaxDynamicSharedMemorySize,
                         FLASH_SMEM_BYTES);

    // fp32 -> bf16 hi/lo conversions
    conv(x, xh, xl, TOKENS * DMODEL);
    conv(q_a_w, wqah, wqal, QLATD * DMODEL);
    conv(q_b_w, wqbh, wqbl, DMODEL * QLATD);
    conv(kv_a_w, wkvh, wkvl, KVLATD * DMODEL);
    conv(k_b_w, wkbh, wkbl, DMODEL * KVLATD);
    conv(v_b_w, wvbh, wvbl, DMODEL * KVLATD);
    conv(o_w, owh, owl, DMODEL * DMODEL);

    // projections on HMMA (3-term bf16 split, cp.async pipelined)
    gemm_mma<<<dim3(QLATD / 128, TOKENS / 128), 256, GEMM_SMEM_BYTES>>>(
        xh, xl, wqah, wqal, nullptr, qlh, qll, TOKENS, QLATD, DMODEL);
    gemm_mma<<<dim3(DMODEL / 128, TOKENS / 128), 256, GEMM_SMEM_BYTES>>>(
        qlh, qll, wqbh, wqbl, q, nullptr, nullptr, TOKENS, DMODEL, QLATD);
    gemm_mma<<<dim3(KVLATD / 128, TOKENS / 128), 256, GEMM_SMEM_BYTES>>>(
        xh, xl, wkvh, wkvl, nullptr, kvh, kvl, TOKENS, KVLATD, DMODEL);
    gemm_mma<<<dim3(DMODEL / 128, TOKENS / 128), 256, GEMM_SMEM_BYTES>>>(
        kvh, kvl, wkbh, wkbl, k, nullptr, nullptr, TOKENS, DMODEL, KVLATD);
    gemm_mma<<<dim3(DMODEL / 128, TOKENS / 128), 256, GEMM_SMEM_BYTES>>>(
        kvh, kvl, wvbh, wvbl, nullptr, vh, vl, TOKENS, DMODEL, KVLATD);

    // per-head RMSNorm + RoPE -> bf16 hi/lo
    norm_rope_kernel<<<TOKENS * NHEADS, 128>>>(q, q_nw, qh, ql);
    norm_rope_kernel<<<TOKENS * NHEADS, 128>>>(k, k_nw, kh, kl);

    // causal flash attention (cp.async K/V pipeline)
    flash_mma<<<dim3(TSEQ / 64, 2 * NHEADS), 256, FLASH_SMEM_BYTES>>>(
        qh, ql, kh, kl, vh, vl, aoh, aol);

    // output projection -> fp32 d_out
    gemm_mma<<<dim3(DMODEL / 128, TOKENS / 128), 256, GEMM_SMEM_BYTES>>>(
        aoh, aol, owh, owl, (float*)d_out, nullptr, nullptr, TOKENS, DMODEL, DMODEL);
}

// round 6
// speedup vs baseline: 2.7150x; 1.0317x over previous
#include <cuda_runtime.h>
#include <cuda_bf16.h>
#include <math.h>
#include <cstdint>

#define TOKENS 4096   // B*T
#define DMODEL 2048   // NH*HD
#define TSEQ   2048
#define NHEADS 16
#define HDIM   128
#define QLATD  1024
#define KVLATD 512

typedef __nv_bfloat16 bf16;

// ---------------- scratch (device globals; no allocation allowed) ----------
__device__ float g_q  [TOKENS * DMODEL];
__device__ float g_k  [TOKENS * DMODEL];
__device__ bf16 g_xh [TOKENS * DMODEL],  g_xl [TOKENS * DMODEL];
__device__ bf16 g_qlh[TOKENS * QLATD],   g_qll[TOKENS * QLATD];
__device__ bf16 g_kvh[TOKENS * KVLATD],  g_kvl[TOKENS * KVLATD];
__device__ bf16 g_qh [TOKENS * DMODEL],  g_ql [TOKENS * DMODEL];
__device__ bf16 g_kh [TOKENS * DMODEL],  g_kl [TOKENS * DMODEL];
__device__ bf16 g_vh [TOKENS * DMODEL],  g_vl [TOKENS * DMODEL];
__device__ bf16 g_aoh[TOKENS * DMODEL],  g_aol[TOKENS * DMODEL];
__device__ bf16 g_wqah[QLATD * DMODEL],  g_wqal[QLATD * DMODEL];
__device__ bf16 g_wqbh[DMODEL * QLATD],  g_wqbl[DMODEL * QLATD];
__device__ bf16 g_wkvh[KVLATD * DMODEL], g_wkvl[KVLATD * DMODEL];
__device__ bf16 g_wkbh[DMODEL * KVLATD], g_wkbl[DMODEL * KVLATD];
__device__ bf16 g_wvbh[DMODEL * KVLATD], g_wvbl[DMODEL * KVLATD];
__device__ bf16 g_owh [DMODEL * DMODEL], g_owl [DMODEL * DMODEL];

// ================= helpers (baseline PTX, no "a"-features) =================
__device__ __forceinline__ uint32_t smem_u32(const void* p) {
    uint32_t a;
    asm("{ .reg .u64 t; cvta.to.shared.u64 t, %1; cvt.u32.u64 %0, t; }"
        : "=r"(a) : "l"(p));
    return a;
}
__device__ __forceinline__ float ex2(float x) {
    float y;
    asm("ex2.approx.ftz.f32 %0, %1;" : "=f"(y) : "f"(x));
    return y;
}

#define CP_ASYNC16(sa, gp) \
    asm volatile("cp.async.cg.shared.global [%0], [%1], 16;" :: "r"(sa), "l"(gp))
#define CP_COMMIT() asm volatile("cp.async.commit_group;" ::: "memory")
#define CP_WAIT0()  asm volatile("cp.async.wait_group 0;" ::: "memory")
#define CP_WAIT1()  asm volatile("cp.async.wait_group 1;" ::: "memory")

#define LDM4(r, addr) \
    asm volatile("ldmatrix.sync.aligned.m8n8.x4.shared.b16 {%0,%1,%2,%3}, [%4];" \
                 : "=r"((r)[0]), "=r"((r)[1]), "=r"((r)[2]), "=r"((r)[3]) : "r"(addr))
#define LDM4T(r, addr) \
    asm volatile("ldmatrix.sync.aligned.m8n8.x4.trans.shared.b16 {%0,%1,%2,%3}, [%4];" \
                 : "=r"((r)[0]), "=r"((r)[1]), "=r"((r)[2]), "=r"((r)[3]) : "r"(addr))
#define MMA_BF16(d, a, b) \
    asm volatile("mma.sync.aligned.m16n8k16.row.col.f32.bf16.bf16.f32 " \
                 "{%0,%1,%2,%3}, {%4,%5,%6,%7}, {%8,%9}, {%0,%1,%2,%3};" \
                 : "+f"((d)[0]), "+f"((d)[1]), "+f"((d)[2]), "+f"((d)[3]) \
                 : "r"((a)[0]), "r"((a)[1]), "r"((a)[2]), "r"((a)[3]), \
                   "r"((b)[0]), "r"((b)[1]))

__device__ __forceinline__ void split2(float v, bf16& h, bf16& l) {
    h = __float2bfloat16_rn(v);
    l = __float2bfloat16_rn(v - __bfloat162float(h));
}
__device__ __forceinline__ void pack_hilo(float a, float b, uint32_t& h, uint32_t& l) {
    bf16 ha, la, hb, lb;
    split2(a, ha, la);
    split2(b, hb, lb);
    __nv_bfloat162 th(ha, hb), tl(la, lb);
    h = *(uint32_t*)&th;
    l = *(uint32_t*)&tl;
}

// ============= tensor-core GEMM: C[M,N] = (Ah+Al)[M,K] * (Bh+Bl)[N,K]^T ====
// 128x128 tile, BK=32, cp.async 2-stage double buffer, 8 warps (2m x 4n).
#define SSTR 40
#define G_ARR  10240
#define G_STG  (4 * G_ARR)
#define GEMM_SMEM_BYTES (2 * G_STG)

__global__ __launch_bounds__(256)
void gemm_mma(const bf16* __restrict__ Ah, const bf16* __restrict__ Al,
              const bf16* __restrict__ Bh, const bf16* __restrict__ Bl,
              float* __restrict__ Cf, bf16* __restrict__ Ch,
              bf16* __restrict__ Cl, int M, int N, int K) {
    extern __shared__ bf16 sg[];
    const uint32_t sb = smem_u32(sg);

    const int tid = threadIdx.x, lane = tid & 31, warp = tid >> 5;
    const int wm = (warp & 1) * 64, wn = (warp >> 1) * 32;
    const int bm = blockIdx.y * 128, bn = blockIdx.x * 128;

    const int lrA = lane & 15, lcA = (lane >> 4) << 3;
    const int l7 = lane & 7;
    const int k8 = ((lane >> 3) & 1) << 3;
    const int n8 = ((lane >> 4) & 1) << 3;

    float c[4][4][4];
#pragma unroll
    for (int i = 0; i < 4; i++)
#pragma unroll
        for (int j = 0; j < 4; j++)
#pragma unroll
            for (int k = 0; k < 4; k++) c[i][j][k] = 0.f;

    auto load_stage = [&](int kt, int s) {
        uint32_t so = sb + (uint32_t)s * G_STG;
#pragma unroll
        for (int i = 0; i < 2; i++) {
            int idx = tid + i * 256;
            int row = idx >> 2, cc = idx & 3;
            size_t gA = (size_t)(bm + row) * K + kt + cc * 8;
            size_t gB = (size_t)(bn + row) * K + kt + cc * 8;
            uint32_t off = (uint32_t)(row * (SSTR * 2) + cc * 16);
            CP_ASYNC16(so + off,             Ah + gA);
            CP_ASYNC16(so + G_ARR + off,     Al + gA);
            CP_ASYNC16(so + 2 * G_ARR + off, Bh + gB);
            CP_ASYNC16(so + 3 * G_ARR + off, Bl + gB);
        }
    };

    const int nkt = K >> 5;
    load_stage(0, 0);
    CP_COMMIT();

    for (int kt = 0; kt < nkt; kt++) {
        if (kt + 1 < nkt) {
            load_stage((kt + 1) << 5, (kt + 1) & 1);
            CP_COMMIT();
            CP_WAIT1();
        } else {
            CP_WAIT0();
        }
        __syncthreads();

        const uint32_t aAh = sb + (uint32_t)(kt & 1) * G_STG;
        const uint32_t aAl = aAh + G_ARR;
        const uint32_t aBh = aAh + 2 * G_ARR;
        const uint32_t aBl = aAh + 3 * G_ARR;

#pragma unroll
        for (int ks = 0; ks < 32; ks += 16) {
            uint32_t bh[4][2], bl[4][2], t[4];
#pragma unroll
            for (int p = 0; p < 2; p++) {
                uint32_t off = (uint32_t)(((wn + p * 16 + n8 + l7) * SSTR + ks + k8) * 2);
                LDM4(t, aBh + off);
                bh[2 * p][0] = t[0]; bh[2 * p][1] = t[1];
                bh[2 * p + 1][0] = t[2]; bh[2 * p + 1][1] = t[3];
                LDM4(t, aBl + off);
                bl[2 * p][0] = t[0]; bl[2 * p][1] = t[1];
                bl[2 * p + 1][0] = t[2]; bl[2 * p + 1][1] = t[3];
            }
#pragma unroll
            for (int mt = 0; mt < 4; mt++) {
                uint32_t off = (uint32_t)(((wm + mt * 16 + lrA) * SSTR + ks + lcA) * 2);
                uint32_t ah[4], al[4];
                LDM4(ah, aAh + off);
                LDM4(al, aAl + off);
#pragma unroll
                for (int nt = 0; nt < 4; nt++) {
                    MMA_BF16(c[mt][nt], ah, bh[nt]);
                    MMA_BF16(c[mt][nt], ah, bl[nt]);
                    MMA_BF16(c[mt][nt], al, bh[nt]);
                }
            }
        }
        __syncthreads();
    }

    const int er = lane >> 2, ec = (lane & 3) << 1;
#pragma unroll
    for (int mt = 0; mt < 4; mt++) {
#pragma unroll
        for (int nt = 0; nt < 4; nt++) {
            size_t r0 = (size_t)(bm + wm + mt * 16 + er);
            int c0 = bn + wn + nt * 8 + ec;
            float v0 = c[mt][nt][0], v1 = c[mt][nt][1];
            float v2 = c[mt][nt][2], v3 = c[mt][nt][3];
            if (Cf) {
                *(float2*)(Cf + r0 * N + c0)       = make_float2(v0, v1);
                *(float2*)(Cf + (r0 + 8) * N + c0) = make_float2(v2, v3);
            }
            if (Ch) {
                uint32_t h01, l01, h23, l23;
                pack_hilo(v0, v1, h01, l01);
                pack_hilo(v2, v3, h23, l23);
                *(uint32_t*)(Ch + r0 * N + c0)       = h01;
                *(uint32_t*)(Ch + (r0 + 8) * N + c0) = h23;
                *(uint32_t*)(Cl + r0 * N + c0)       = l01;
                *(uint32_t*)(Cl + (r0 + 8) * N + c0) = l23;
            }
        }
    }
}

// ---------------- fp32 -> (bf16 hi, bf16 lo) ------------------------------
__global__ __launch_bounds__(256)
void conv_hilo(const float* __restrict__ in, bf16* __restrict__ hi,
               bf16* __restrict__ lo, int n4) {
    int i = blockIdx.x * 256 + threadIdx.x;
    if (i >= n4) return;
    float4 x = ((const float4*)in)[i];
    float v[4] = {x.x, x.y, x.z, x.w};
    bf16 h[4], l[4];
#pragma unroll
    for (int j = 0; j < 4; j++) split2(v[j], h[j], l[j]);
    ((__nv_bfloat162*)hi)[i * 2]     = __nv_bfloat162(h[0], h[1]);
    ((__nv_bfloat162*)hi)[i * 2 + 1] = __nv_bfloat162(h[2], h[3]);
    ((__nv_bfloat162*)lo)[i * 2]     = __nv_bfloat162(l[0], l[1]);
    ((__nv_bfloat162*)lo)[i * 2 + 1] = __nv_bfloat162(l[2], l[3]);
}

// -------- fused per-head RMSNorm + RoPE, emitting bf16 hi/lo ---------------
__global__ __launch_bounds__(128)
void norm_rope_kernel(const float* __restrict__ X, const float* __restrict__ w,
                      bf16* __restrict__ H, bf16* __restrict__ L) {
    const int blk = blockIdx.x;
    const int token = blk >> 4, h = blk & 15;
    const int t = token & (TSEQ - 1);
    const int i = threadIdx.x;
    const size_t off = (size_t)token * DMODEL + h * HDIM + i;
    float x = X[off];
    float ss = x * x;
#pragma unroll
    for (int o = 16; o; o >>= 1)
        ss += __shfl_xor_sync(0xffffffffu, ss, o);
    __shared__ float sred[4];
    if ((i & 31) == 0) sred[i >> 5] = ss;
    __syncthreads();
    ss = sred[0] + sred[1] + sred[2] + sred[3];
    float rn = rsqrtf(ss * (1.0f / HDIM) + 1e-6f);
    float xn = x * rn * w[i];
    __shared__ float sh[HDIM];
    sh[i] = xn;
    __syncthreads();
    const int f = i & 63;
    float invf = exp2f((float)f * (-13.287712379549449f / 64.0f));
    float ang = (float)t * invf;
    float c, s;
    sincosf(ang, &s, &c);
    float partner = (i < 64) ? -sh[i + 64] : sh[i - 64];
    float out = xn * c + partner * s;
    bf16 hh, ll;
    split2(out, hh, ll);
    H[off] = hh;
    L[off] = ll;
}

// ======== causal flash attention v2: BQ=128, BKV=64, register-resident P ===
// 8 warps all in m: warp owns S rows [warp*16, +16) x all 64 KV cols.
// Softmax warp-local; P packed hi/lo in registers (FA2 C->A fragment reuse).
#define QK_STR 136         // bf16 units (272 B rows): conflict-free ldmatrix
#define FQ_H 0             // Q hi : 128*136*2 = 34816 B
#define FQ_L 34816
#define FKV0 69632         // KV stages
#define FKVS 69632
#define SK_H 0
#define SK_L 17408         // 64*136*2
#define SV_H 34816
#define SV_L 52224
#define FLASH_SMEM_BYTES 208896
#define SCL 0.1275175f     // (1/sqrt(128)) * log2(e)

__global__ __launch_bounds__(256, 1)
void flash_mma(const bf16* __restrict__ Qh, const bf16* __restrict__ Ql,
               const bf16* __restrict__ Kh, const bf16* __restrict__ Kl,
               const bf16* __restrict__ Vh, const bf16* __restrict__ Vl,
               bf16* __restrict__ Oh, bf16* __restrict__ Ol) {
    extern __shared__ char smraw[];
    const uint32_t sb = smem_u32(smraw);

    const int qb = blockIdx.x;
    const int pair = blockIdx.y;
    const int b = pair >> 4, h = pair & 15;
    const int tid = threadIdx.x, lane = tid & 31, warp = tid >> 5;
    const int wm = warp * 16;
    const int er = lane >> 2, ec = (lane & 3) << 1;
    const int lrA = lane & 15, lcA = (lane >> 4) << 3;
    const int l7 = lane & 7;
    const int k8 = ((lane >> 3) & 1) << 3;
    const int n8 = ((lane >> 4) & 1) << 3;

    const size_t bT = (size_t)b * TSEQ;
    const int hoff = h * HDIM;

    // ---- async load Q tile (128 x 128, hi/lo) ----
#pragma unroll
    for (int i = 0; i < 8; i++) {
        int idx = tid + i * 256;
        int row = idx >> 4, ch = idx & 15;
        size_t g = (bT + qb * 128 + row) * DMODEL + hoff + ch * 8;
        uint32_t off = (uint32_t)(row * (QK_STR * 2) + ch * 16);
        CP_ASYNC16(sb + FQ_H + off, Qh + g);
        CP_ASYNC16(sb + FQ_L + off, Ql + g);
    }
    auto load_kv = [&](int kb, int s) {
        uint32_t so = sb + FKV0 + (uint32_t)s * FKVS;
#pragma unroll
        for (int i = 0; i < 4; i++) {
            int idx = tid + i * 256;
            int row = idx >> 4, ch = idx & 15;
            size_t g = (bT + kb * 64 + row) * DMODEL + hoff + ch * 8;
            uint32_t off = (uint32_t)(row * (QK_STR * 2) + ch * 16);
            CP_ASYNC16(so + SK_H + off, Kh + g);
            CP_ASYNC16(so + SK_L + off, Kl + g);
            CP_ASYNC16(so + SV_H + off, Vh + g);
            CP_ASYNC16(so + SV_L + off, Vl + g);
        }
    };
    load_kv(0, 0);
    CP_COMMIT();

    float o[16][4];
#pragma unroll
    for (int i = 0; i < 16; i++)
#pragma unroll
        for (int j = 0; j < 4; j++) o[i][j] = 0.f;
    float m0 = -1e30f, m1 = -1e30f, l0 = 0.f, l1 = 0.f;

    const int grow_lo = qb * 128 + wm + er;
    const int grow_hi = grow_lo + 8;
    const int row_max = qb * 128 + wm + 15;
    const int nkb = 2 * qb + 2;

    for (int kb = 0; kb < nkb; kb++) {
        if (kb + 1 < nkb) {
            load_kv(kb + 1, (kb + 1) & 1);
            CP_COMMIT();
            CP_WAIT1();
        } else {
            CP_WAIT0();
        }
        __syncthreads();

        if (kb * 64 <= row_max) {   // causal per-warp skip
            const uint32_t sKV = sb + FKV0 + (uint32_t)(kb & 1) * FKVS;
            const uint32_t sKh = sKV + SK_H, sKl = sKV + SK_L;
            const uint32_t sVh = sKV + SV_H, sVl = sKV + SV_L;

            // ---- S = Q K^T (3-term split), warp tile 16 x 64 ----
            float c[8][4];
#pragma unroll
            for (int i = 0; i < 8; i++)
#pragma unroll
                for (int j = 0; j < 4; j++) c[i][j] = 0.f;

#pragma unroll
            for (int ks = 0; ks < 8; ks++) {
                uint32_t ah[4], al[4];
                uint32_t offA = (uint32_t)(((wm + lrA) * QK_STR + ks * 16 + lcA) * 2);
                LDM4(ah, sb + FQ_H + offA);
                LDM4(al, sb + FQ_L + offA);
                uint32_t bh[8][2], bl[8][2], t[4];
#pragma unroll
                for (int p = 0; p < 4; p++) {
                    uint32_t offB = (uint32_t)(((p * 16 + n8 + l7) * QK_STR + ks * 16 + k8) * 2);
                    LDM4(t, sKh + offB);
                    bh[2 * p][0] = t[0]; bh[2 * p][1] = t[1];
                    bh[2 * p + 1][0] = t[2]; bh[2 * p + 1][1] = t[3];
                    LDM4(t, sKl + offB);
                    bl[2 * p][0] = t[0]; bl[2 * p][1] = t[1];
                    bl[2 * p + 1][0] = t[2]; bl[2 * p + 1][1] = t[3];
                }
#pragma unroll
                for (int nt = 0; nt < 8; nt++) {
                    MMA_BF16(c[nt], ah, bh[nt]);
                    MMA_BF16(c[nt], ah, bl[nt]);
                    MMA_BF16(c[nt], al, bh[nt]);
                }
            }

            // ---- warp-local softmax (base-2 domain) ----
            float mx0 = -1e30f, mx1 = -1e30f;
#pragma unroll
            for (int nt = 0; nt < 8; nt++) {
                int col = kb * 64 + nt * 8 + ec;
#pragma unroll
                for (int j = 0; j < 2; j++) {
                    float s0 = c[nt][j] * SCL;
                    float s1 = c[nt][j + 2] * SCL;
                    if (col + j > grow_lo) s0 = -1e30f;
                    if (col + j > grow_hi) s1 = -1e30f;
                    c[nt][j] = s0; c[nt][j + 2] = s1;
                    mx0 = fmaxf(mx0, s0); mx1 = fmaxf(mx1, s1);
                }
            }
            mx0 = fmaxf(mx0, __shfl_xor_sync(0xffffffffu, mx0, 1));
            mx0 = fmaxf(mx0, __shfl_xor_sync(0xffffffffu, mx0, 2));
            mx1 = fmaxf(mx1, __shfl_xor_sync(0xffffffffu, mx1, 1));
            mx1 = fmaxf(mx1, __shfl_xor_sync(0xffffffffu, mx1, 2));
            float m0n = fmaxf(m0, mx0), m1n = fmaxf(m1, mx1);
            float a0 = ex2(m0 - m0n), a1 = ex2(m1 - m1n);
            m0 = m0n; m1 = m1n;

            float sum0 = 0.f, sum1 = 0.f;
#pragma unroll
            for (int nt = 0; nt < 8; nt++) {
                float p0 = ex2(c[nt][0] - m0n), p1 = ex2(c[nt][1] - m0n);
                float p2 = ex2(c[nt][2] - m1n), p3 = ex2(c[nt][3] - m1n);
                c[nt][0] = p0; c[nt][1] = p1; c[nt][2] = p2; c[nt][3] = p3;
                sum0 += p0 + p1; sum1 += p2 + p3;
            }
            sum0 += __shfl_xor_sync(0xffffffffu, sum0, 1);
            sum0 += __shfl_xor_sync(0xffffffffu, sum0, 2);
            sum1 += __shfl_xor_sync(0xffffffffu, sum1, 1);
            sum1 += __shfl_xor_sync(0xffffffffu, sum1, 2);
            l0 = l0 * a0 + sum0;
            l1 = l1 * a1 + sum1;
#pragma unroll
            for (int nt = 0; nt < 16; nt++) {
                o[nt][0] *= a0; o[nt][1] *= a0;
                o[nt][2] *= a1; o[nt][3] *= a1;
            }

            // ---- O += P V (3-term split), P built in registers ----
#pragma unroll
            for (int kk = 0; kk < 4; kk++) {
                uint32_t ph[4], pl[4];
                pack_hilo(c[2 * kk][0],     c[2 * kk][1],     ph[0], pl[0]);
                pack_hilo(c[2 * kk][2],     c[2 * kk][3],     ph[1], pl[1]);
                pack_hilo(c[2 * kk + 1][0], c[2 * kk + 1][1], ph[2], pl[2]);
                pack_hilo(c[2 * kk + 1][2], c[2 * kk + 1][3], ph[3], pl[3]);
#pragma unroll
                for (int p = 0; p < 8; p++) {
                    uint32_t vh[4], vl[4];
                    uint32_t offV = (uint32_t)(((kk * 16 + l7 + k8) * QK_STR + p * 16 + n8) * 2);
                    LDM4T(vh, sVh + offV);
                    LDM4T(vl, sVl + offV);
                    uint32_t vh0[2] = {vh[0], vh[1]}, vh1[2] = {vh[2], vh[3]};
                    uint32_t vl0[2] = {vl[0], vl[1]}, vl1[2] = {vl[2], vl[3]};
                    MMA_BF16(o[2 * p], ph, vh0);
                    MMA_BF16(o[2 * p], pl, vh0);
                    MMA_BF16(o[2 * p], ph, vl0);
                    MMA_BF16(o[2 * p + 1], ph, vh1);
                    MMA_BF16(o[2 * p + 1], pl, vh1);
                    MMA_BF16(o[2 * p + 1], ph, vl1);
                }
            }
        }
        __syncthreads();   // all reads of this stage done before next prefetch
    }

    // ---- normalize + write hi/lo O ----
    float inv0 = 1.f / l0, inv1 = 1.f / l1;
    size_t tok_lo = (bT + (size_t)grow_lo) * DMODEL + hoff;
    size_t tok_hi = (bT + (size_t)grow_hi) * DMODEL + hoff;
#pragma unroll
    for (int nt = 0; nt < 16; nt++) {
        int col = nt * 8 + ec;
        float v0 = o[nt][0] * inv0, v1 = o[nt][1] * inv0;
        float v2 = o[nt][2] * inv1, v3 = o[nt][3] * inv1;
        uint32_t h01, l01, h23, l23;
        pack_hilo(v0, v1, h01, l01);
        pack_hilo(v2, v3, h23, l23);
        *(uint32_t*)(Oh + tok_lo + col) = h01;
        *(uint32_t*)(Oh + tok_hi + col) = h23;
        *(uint32_t*)(Ol + tok_lo + col) = l01;
        *(uint32_t*)(Ol + tok_hi + col) = l23;
    }
}

// ---------------- launch ----------------------------------------------------
static inline void conv(const float* in, bf16* h, bf16* l, int n) {
    int n4 = n / 4;
    conv_hilo<<<(n4 + 255) / 256, 256>>>(in, h, l, n4);
}

extern "C" void kernel_launch(void* const* d_in, const int* in_sizes, int n_in,
                              void* d_out, int out_size) {
    const float* x      = (const float*)d_in[0];
    const float* q_a_w  = (const float*)d_in[2];
    const float* q_b_w  = (const float*)d_in[3];
    const float* kv_a_w = (const float*)d_in[4];
    const float* k_b_w  = (const float*)d_in[5];
    const float* v_b_w  = (const float*)d_in[6];
    const float* o_w    = (const float*)d_in[7];
    const float* q_nw   = (const float*)d_in[8];
    const float* k_nw   = (const float*)d_in[9];

    float *q, *k;
    bf16 *xh, *xl, *qlh, *qll, *kvh, *kvl;
    bf16 *qh, *ql, *kh, *kl, *vh, *vl, *aoh, *aol;
    bf16 *wqah, *wqal, *wqbh, *wqbl, *wkvh, *wkvl, *wkbh, *wkbl, *wvbh, *wvbl, *owh, *owl;
    cudaGetSymbolAddress((void**)&q, g_q);     cudaGetSymbolAddress((void**)&k, g_k);
    cudaGetSymbolAddress((void**)&xh, g_xh);   cudaGetSymbolAddress((void**)&xl, g_xl);
    cudaGetSymbolAddress((void**)&qlh, g_qlh); cudaGetSymbolAddress((void**)&qll, g_qll);
    cudaGetSymbolAddress((void**)&kvh, g_kvh); cudaGetSymbolAddress((void**)&kvl, g_kvl);
    cudaGetSymbolAddress((void**)&qh, g_qh);   cudaGetSymbolAddress((void**)&ql, g_ql);
    cudaGetSymbolAddress((void**)&kh, g_kh);   cudaGetSymbolAddress((void**)&kl, g_kl);
    cudaGetSymbolAddress((void**)&vh, g_vh);   cudaGetSymbolAddress((void**)&vl, g_vl);
    cudaGetSymbolAddress((void**)&aoh, g_aoh); cudaGetSymbolAddress((void**)&aol, g_aol);
    cudaGetSymbolAddress((void**)&wqah, g_wqah); cudaGetSymbolAddress((void**)&wqal, g_wqal);
    cudaGetSymbolAddress((void**)&wqbh, g_wqbh); cudaGetSymbolAddress((void**)&wqbl, g_wqbl);
    cudaGetSymbolAddress((void**)&wkvh, g_wkvh); cudaGetSymbolAddress((void**)&wkvl, g_wkvl);
    cudaGetSymbolAddress((void**)&wkbh, g_wkbh); cudaGetSymbolAddress((void**)&wkbl, g_wkbl);
    cudaGetSymbolAddress((void**)&wvbh, g_wvbh); cudaGetSymbolAddress((void**)&wvbl, g_wvbl);
    cudaGetSymbolAddress((void**)&owh, g_owh);   cudaGetSymbolAddress((void**)&owl, g_owl);

    cudaFuncSetAttribute(gemm_mma, cudaFuncAttributeMaxDynamicSharedMemorySize,
                         GEMM_SMEM_BYTES);
    cudaFuncSetAttribute(flash_mma, cudaFuncAttributeMaxDynamicSharedMemorySize,
                         FLASH_SMEM_BYTES);

    // fp32 -> bf16 hi/lo conversions
    conv(x, xh, xl, TOKENS * DMODEL);
    conv(q_a_w, wqah, wqal, QLATD * DMODEL);
    conv(q_b_w, wqbh, wqbl, DMODEL * QLATD);
    conv(kv_a_w, wkvh, wkvl, KVLATD * DMODEL);
    conv(k_b_w, wkbh, wkbl, DMODEL * KVLATD);
    conv(v_b_w, wvbh, wvbl, DMODEL * KVLATD);
    conv(o_w, owh, owl, DMODEL * DMODEL);

    // projections on HMMA (3-term bf16 split, cp.async pipelined)
    gemm_mma<<<dim3(QLATD / 128, TOKENS / 128), 256, GEMM_SMEM_BYTES>>>(
        xh, xl, wqah, wqal, nullptr, qlh, qll, TOKENS, QLATD, DMODEL);
    gemm_mma<<<dim3(DMODEL / 128, TOKENS / 128), 256, GEMM_SMEM_BYTES>>>(
        qlh, qll, wqbh, wqbl, q, nullptr, nullptr, TOKENS, DMODEL, QLATD);
    gemm_mma<<<dim3(KVLATD / 128, TOKENS / 128), 256, GEMM_SMEM_BYTES>>>(
        xh, xl, wkvh, wkvl, nullptr, kvh, kvl, TOKENS, KVLATD, DMODEL);
    gemm_mma<<<dim3(DMODEL / 128, TOKENS / 128), 256, GEMM_SMEM_BYTES>>>(
        kvh, kvl, wkbh, wkbl, k, nullptr, nullptr, TOKENS, DMODEL, KVLATD);
    gemm_mma<<<dim3(DMODEL / 128, TOKENS / 128), 256, GEMM_SMEM_BYTES>>>(
        kvh, kvl, wvbh, wvbl, nullptr, vh, vl, TOKENS, DMODEL, KVLATD);

    // per-head RMSNorm + RoPE -> bf16 hi/lo
    norm_rope_kernel<<<TOKENS * NHEADS, 128>>>(q, q_nw, qh, ql);
    norm_rope_kernel<<<TOKENS * NHEADS, 128>>>(k, k_nw, kh, kl);

    // causal flash attention v2 (BQ=128, register P, warp-local softmax)
    flash_mma<<<dim3(TSEQ / 128, 2 * NHEADS), 256, FLASH_SMEM_BYTES>>>(
        qh, ql, kh, kl, vh, vl, aoh, aol);

    // output projection -> fp32 d_out
    gemm_mma<<<dim3(DMODEL / 128, TOKENS / 128), 256, GEMM_SMEM_BYTES>>>(
        aoh, aol, owh, owl, (float*)d_out, nullptr, nullptr, TOKENS, DMODEL, DMODEL);
}

// round 7
// speedup vs baseline: 2.7772x; 1.0229x over previous
#include <cuda_runtime.h>
#include <cuda_bf16.h>
#include <math.h>
#include <cstdint>

#define TOKENS 4096   // B*T
#define DMODEL 2048   // NH*HD
#define TSEQ   2048
#define NHEADS 16
#define HDIM   128
#define QLATD  1024
#define KVLATD 512

typedef __nv_bfloat16 bf16;

// ---------------- scratch (device globals; no allocation allowed) ----------
__device__ float g_q  [TOKENS * DMODEL];
__device__ float g_k  [TOKENS * DMODEL];
__device__ bf16 g_xh [TOKENS * DMODEL],  g_xl [TOKENS * DMODEL];
__device__ bf16 g_qlh[TOKENS * QLATD],   g_qll[TOKENS * QLATD];
__device__ bf16 g_kvh[TOKENS * KVLATD],  g_kvl[TOKENS * KVLATD];
__device__ bf16 g_qh [TOKENS * DMODEL],  g_ql [TOKENS * DMODEL];
__device__ bf16 g_kh [TOKENS * DMODEL],  g_kl [TOKENS * DMODEL];
__device__ bf16 g_vh [TOKENS * DMODEL],  g_vl [TOKENS * DMODEL];
__device__ bf16 g_aoh[TOKENS * DMODEL],  g_aol[TOKENS * DMODEL];
__device__ bf16 g_wqah[QLATD * DMODEL],  g_wqal[QLATD * DMODEL];
__device__ bf16 g_wqbh[DMODEL * QLATD],  g_wqbl[DMODEL * QLATD];
__device__ bf16 g_wkvh[KVLATD * DMODEL], g_wkvl[KVLATD * DMODEL];
__device__ bf16 g_wkbh[DMODEL * KVLATD], g_wkbl[DMODEL * KVLATD];
__device__ bf16 g_wvbh[DMODEL * KVLATD], g_wvbl[DMODEL * KVLATD];
__device__ bf16 g_owh [DMODEL * DMODEL], g_owl [DMODEL * DMODEL];

// ================= helpers (baseline PTX, no "a"-features) =================
__device__ __forceinline__ uint32_t smem_u32(const void* p) {
    uint32_t a;
    asm("{ .reg .u64 t; cvta.to.shared.u64 t, %1; cvt.u32.u64 %0, t; }"
        : "=r"(a) : "l"(p));
    return a;
}
__device__ __forceinline__ float ex2(float x) {
    float y;
    asm("ex2.approx.ftz.f32 %0, %1;" : "=f"(y) : "f"(x));
    return y;
}

#define CP_ASYNC16(sa, gp) \
    asm volatile("cp.async.cg.shared.global [%0], [%1], 16;" :: "r"(sa), "l"(gp))
#define CP_COMMIT() asm volatile("cp.async.commit_group;" ::: "memory")
#define CP_WAIT0()  asm volatile("cp.async.wait_group 0;" ::: "memory")
#define CP_WAIT1()  asm volatile("cp.async.wait_group 1;" ::: "memory")

#define LDM4(r, addr) \
    asm volatile("ldmatrix.sync.aligned.m8n8.x4.shared.b16 {%0,%1,%2,%3}, [%4];" \
                 : "=r"((r)[0]), "=r"((r)[1]), "=r"((r)[2]), "=r"((r)[3]) : "r"(addr))
#define LDM4T(r, addr) \
    asm volatile("ldmatrix.sync.aligned.m8n8.x4.trans.shared.b16 {%0,%1,%2,%3}, [%4];" \
                 : "=r"((r)[0]), "=r"((r)[1]), "=r"((r)[2]), "=r"((r)[3]) : "r"(addr))
#define MMA_BF16(d, a, b) \
    asm volatile("mma.sync.aligned.m16n8k16.row.col.f32.bf16.bf16.f32 " \
                 "{%0,%1,%2,%3}, {%4,%5,%6,%7}, {%8,%9}, {%0,%1,%2,%3};" \
                 : "+f"((d)[0]), "+f"((d)[1]), "+f"((d)[2]), "+f"((d)[3]) \
                 : "r"((a)[0]), "r"((a)[1]), "r"((a)[2]), "r"((a)[3]), \
                   "r"((b)[0]), "r"((b)[1]))

__device__ __forceinline__ void split2(float v, bf16& h, bf16& l) {
    h = __float2bfloat16_rn(v);
    l = __float2bfloat16_rn(v - __bfloat162float(h));
}
__device__ __forceinline__ void pack_hilo(float a, float b, uint32_t& h, uint32_t& l) {
    bf16 ha, la, hb, lb;
    split2(a, ha, la);
    split2(b, hb, lb);
    __nv_bfloat162 th(ha, hb), tl(la, lb);
    h = *(uint32_t*)&th;
    l = *(uint32_t*)&tl;
}

// ============= tensor-core GEMM: C[M,N] = (Ah+Al)[M,K] * (Bh+Bl)[N,K]^T ====
// 128x128 tile, BK=32, cp.async 2-stage, 4 warps each 64x64 (high smem AI).
#define SSTR 40
#define G_ARR  10240
#define G_STG  (4 * G_ARR)
#define GEMM_SMEM_BYTES (2 * G_STG)

__global__ __launch_bounds__(128)
void gemm_mma(const bf16* __restrict__ Ah, const bf16* __restrict__ Al,
              const bf16* __restrict__ Bh, const bf16* __restrict__ Bl,
              float* __restrict__ Cf, bf16* __restrict__ Ch,
              bf16* __restrict__ Cl, int M, int N, int K) {
    extern __shared__ bf16 sg[];
    const uint32_t sb = smem_u32(sg);

    const int tid = threadIdx.x, lane = tid & 31, warp = tid >> 5;
    const int wm = (warp & 1) * 64, wn = (warp >> 1) * 64;
    const int bm = blockIdx.y * 128, bn = blockIdx.x * 128;

    const int lrA = lane & 15, lcA = (lane >> 4) << 3;
    const int l7 = lane & 7;
    const int k8 = ((lane >> 3) & 1) << 3;
    const int n8 = ((lane >> 4) & 1) << 3;

    float c[4][8][4];
#pragma unroll
    for (int i = 0; i < 4; i++)
#pragma unroll
        for (int j = 0; j < 8; j++)
#pragma unroll
            for (int k = 0; k < 4; k++) c[i][j][k] = 0.f;

    auto load_stage = [&](int kt, int s) {
        uint32_t so = sb + (uint32_t)s * G_STG;
#pragma unroll
        for (int i = 0; i < 4; i++) {
            int idx = tid + i * 128;                 // 512 chunks per array
            int row = idx >> 2, cc = idx & 3;
            size_t gA = (size_t)(bm + row) * K + kt + cc * 8;
            size_t gB = (size_t)(bn + row) * K + kt + cc * 8;
            uint32_t off = (uint32_t)(row * (SSTR * 2) + cc * 16);
            CP_ASYNC16(so + off,             Ah + gA);
            CP_ASYNC16(so + G_ARR + off,     Al + gA);
            CP_ASYNC16(so + 2 * G_ARR + off, Bh + gB);
            CP_ASYNC16(so + 3 * G_ARR + off, Bl + gB);
        }
    };

    const int nkt = K >> 5;
    load_stage(0, 0);
    CP_COMMIT();

    for (int kt = 0; kt < nkt; kt++) {
        if (kt + 1 < nkt) {
            load_stage((kt + 1) << 5, (kt + 1) & 1);
            CP_COMMIT();
            CP_WAIT1();
        } else {
            CP_WAIT0();
        }
        __syncthreads();

        const uint32_t aAh = sb + (uint32_t)(kt & 1) * G_STG;
        const uint32_t aAl = aAh + G_ARR;
        const uint32_t aBh = aAh + 2 * G_ARR;
        const uint32_t aBl = aAh + 3 * G_ARR;

#pragma unroll
        for (int ks = 0; ks < 32; ks += 16) {
            uint32_t bh[8][2], bl[8][2], t[4];
#pragma unroll
            for (int p = 0; p < 4; p++) {
                uint32_t off = (uint32_t)(((wn + p * 16 + n8 + l7) * SSTR + ks + k8) * 2);
                LDM4(t, aBh + off);
                bh[2 * p][0] = t[0]; bh[2 * p][1] = t[1];
                bh[2 * p + 1][0] = t[2]; bh[2 * p + 1][1] = t[3];
                LDM4(t, aBl + off);
                bl[2 * p][0] = t[0]; bl[2 * p][1] = t[1];
                bl[2 * p + 1][0] = t[2]; bl[2 * p + 1][1] = t[3];
            }
#pragma unroll
            for (int mt = 0; mt < 4; mt++) {
                uint32_t off = (uint32_t)(((wm + mt * 16 + lrA) * SSTR + ks + lcA) * 2);
                uint32_t ah[4], al[4];
                LDM4(ah, aAh + off);
                LDM4(al, aAl + off);
#pragma unroll
                for (int nt = 0; nt < 8; nt++) {
                    MMA_BF16(c[mt][nt], ah, bh[nt]);
                    MMA_BF16(c[mt][nt], ah, bl[nt]);
                    MMA_BF16(c[mt][nt], al, bh[nt]);
                }
            }
        }
        __syncthreads();
    }

    const int er = lane >> 2, ec = (lane & 3) << 1;
#pragma unroll
    for (int mt = 0; mt < 4; mt++) {
#pragma unroll
        for (int nt = 0; nt < 8; nt++) {
            size_t r0 = (size_t)(bm + wm + mt * 16 + er);
            int c0 = bn + wn + nt * 8 + ec;
            float v0 = c[mt][nt][0], v1 = c[mt][nt][1];
            float v2 = c[mt][nt][2], v3 = c[mt][nt][3];
            if (Cf) {
                *(float2*)(Cf + r0 * N + c0)       = make_float2(v0, v1);
                *(float2*)(Cf + (r0 + 8) * N + c0) = make_float2(v2, v3);
            }
            if (Ch) {
                uint32_t h01, l01, h23, l23;
                pack_hilo(v0, v1, h01, l01);
                pack_hilo(v2, v3, h23, l23);
                *(uint32_t*)(Ch + r0 * N + c0)       = h01;
                *(uint32_t*)(Ch + (r0 + 8) * N + c0) = h23;
                *(uint32_t*)(Cl + r0 * N + c0)       = l01;
                *(uint32_t*)(Cl + (r0 + 8) * N + c0) = l23;
            }
        }
    }
}

// ---------------- fp32 -> (bf16 hi, bf16 lo) ------------------------------
__global__ __launch_bounds__(256)
void conv_hilo(const float* __restrict__ in, bf16* __restrict__ hi,
               bf16* __restrict__ lo, int n4) {
    int i = blockIdx.x * 256 + threadIdx.x;
    if (i >= n4) return;
    float4 x = ((const float4*)in)[i];
    float v[4] = {x.x, x.y, x.z, x.w};
    bf16 h[4], l[4];
#pragma unroll
    for (int j = 0; j < 4; j++) split2(v[j], h[j], l[j]);
    ((__nv_bfloat162*)hi)[i * 2]     = __nv_bfloat162(h[0], h[1]);
    ((__nv_bfloat162*)hi)[i * 2 + 1] = __nv_bfloat162(h[2], h[3]);
    ((__nv_bfloat162*)lo)[i * 2]     = __nv_bfloat162(l[0], l[1]);
    ((__nv_bfloat162*)lo)[i * 2 + 1] = __nv_bfloat162(l[2], l[3]);
}

// -------- fused per-head RMSNorm + RoPE, emitting bf16 hi/lo ---------------
__global__ __launch_bounds__(128)
void norm_rope_kernel(const float* __restrict__ X, const float* __restrict__ w,
                      bf16* __restrict__ H, bf16* __restrict__ L) {
    const int blk = blockIdx.x;
    const int token = blk >> 4, h = blk & 15;
    const int t = token & (TSEQ - 1);
    const int i = threadIdx.x;
    const size_t off = (size_t)token * DMODEL + h * HDIM + i;
    float x = X[off];
    float ss = x * x;
#pragma unroll
    for (int o = 16; o; o >>= 1)
        ss += __shfl_xor_sync(0xffffffffu, ss, o);
    __shared__ float sred[4];
    if ((i & 31) == 0) sred[i >> 5] = ss;
    __syncthreads();
    ss = sred[0] + sred[1] + sred[2] + sred[3];
    float rn = rsqrtf(ss * (1.0f / HDIM) + 1e-6f);
    float xn = x * rn * w[i];
    __shared__ float sh[HDIM];
    sh[i] = xn;
    __syncthreads();
    const int f = i & 63;
    float invf = exp2f((float)f * (-13.287712379549449f / 64.0f));
    float ang = (float)t * invf;
    float c, s;
    sincosf(ang, &s, &c);
    float partner = (i < 64) ? -sh[i + 64] : sh[i - 64];
    float out = xn * c + partner * s;
    bf16 hh, ll;
    split2(out, hh, ll);
    H[off] = hh;
    L[off] = ll;
}

// ======== causal flash attention v2: BQ=128, BKV=64, register-resident P ===
#define QK_STR 136
#define FQ_H 0
#define FQ_L 34816
#define FKV0 69632
#define FKVS 69632
#define SK_H 0
#define SK_L 17408
#define SV_H 34816
#define SV_L 52224
#define FLASH_SMEM_BYTES 208896
#define SCL 0.1275175f     // (1/sqrt(128)) * log2(e)

__global__ __launch_bounds__(256, 1)
void flash_mma(const bf16* __restrict__ Qh, const bf16* __restrict__ Ql,
               const bf16* __restrict__ Kh, const bf16* __restrict__ Kl,
               const bf16* __restrict__ Vh, const bf16* __restrict__ Vl,
               bf16* __restrict__ Oh, bf16* __restrict__ Ol) {
    extern __shared__ char smraw[];
    const uint32_t sb = smem_u32(smraw);

    const int qb = (TSEQ / 128 - 1) - blockIdx.x;   // heavy CTAs first
    const int pair = blockIdx.y;
    const int b = pair >> 4, h = pair & 15;
    const int tid = threadIdx.x, lane = tid & 31, warp = tid >> 5;
    const int wm = warp * 16;
    const int er = lane >> 2, ec = (lane & 3) << 1;
    const int lrA = lane & 15, lcA = (lane >> 4) << 3;
    const int l7 = lane & 7;
    const int k8 = ((lane >> 3) & 1) << 3;
    const int n8 = ((lane >> 4) & 1) << 3;

    const size_t bT = (size_t)b * TSEQ;
    const int hoff = h * HDIM;

#pragma unroll
    for (int i = 0; i < 8; i++) {
        int idx = tid + i * 256;
        int row = idx >> 4, ch = idx & 15;
        size_t g = (bT + qb * 128 + row) * DMODEL + hoff + ch * 8;
        uint32_t off = (uint32_t)(row * (QK_STR * 2) + ch * 16);
        CP_ASYNC16(sb + FQ_H + off, Qh + g);
        CP_ASYNC16(sb + FQ_L + off, Ql + g);
    }
    auto load_kv = [&](int kb, int s) {
        uint32_t so = sb + FKV0 + (uint32_t)s * FKVS;
#pragma unroll
        for (int i = 0; i < 4; i++) {
            int idx = tid + i * 256;
            int row = idx >> 4, ch = idx & 15;
            size_t g = (bT + kb * 64 + row) * DMODEL + hoff + ch * 8;
            uint32_t off = (uint32_t)(row * (QK_STR * 2) + ch * 16);
            CP_ASYNC16(so + SK_H + off, Kh + g);
            CP_ASYNC16(so + SK_L + off, Kl + g);
            CP_ASYNC16(so + SV_H + off, Vh + g);
            CP_ASYNC16(so + SV_L + off, Vl + g);
        }
    };
    load_kv(0, 0);
    CP_COMMIT();

    float o[16][4];
#pragma unroll
    for (int i = 0; i < 16; i++)
#pragma unroll
        for (int j = 0; j < 4; j++) o[i][j] = 0.f;
    float m0 = -1e30f, m1 = -1e30f, l0 = 0.f, l1 = 0.f;

    const int grow_lo = qb * 128 + wm + er;
    const int grow_hi = grow_lo + 8;
    const int row_max = qb * 128 + wm + 15;
    const int nkb = 2 * qb + 2;

    for (int kb = 0; kb < nkb; kb++) {
        if (kb + 1 < nkb) {
            load_kv(kb + 1, (kb + 1) & 1);
            CP_COMMIT();
            CP_WAIT1();
        } else {
            CP_WAIT0();
        }
        __syncthreads();

        if (kb * 64 <= row_max) {   // causal per-warp skip
            const uint32_t sKV = sb + FKV0 + (uint32_t)(kb & 1) * FKVS;
            const uint32_t sKh = sKV + SK_H, sKl = sKV + SK_L;
            const uint32_t sVh = sKV + SV_H, sVl = sKV + SV_L;

            float c[8][4];
#pragma unroll
            for (int i = 0; i < 8; i++)
#pragma unroll
                for (int j = 0; j < 4; j++) c[i][j] = 0.f;

#pragma unroll
            for (int ks = 0; ks < 8; ks++) {
                uint32_t ah[4], al[4];
                uint32_t offA = (uint32_t)(((wm + lrA) * QK_STR + ks * 16 + lcA) * 2);
                LDM4(ah, sb + FQ_H + offA);
                LDM4(al, sb + FQ_L + offA);
                uint32_t bh[8][2], bl[8][2], t[4];
#pragma unroll
                for (int p = 0; p < 4; p++) {
                    uint32_t offB = (uint32_t)(((p * 16 + n8 + l7) * QK_STR + ks * 16 + k8) * 2);
                    LDM4(t, sKh + offB);
                    bh[2 * p][0] = t[0]; bh[2 * p][1] = t[1];
                    bh[2 * p + 1][0] = t[2]; bh[2 * p + 1][1] = t[3];
                    LDM4(t, sKl + offB);
                    bl[2 * p][0] = t[0]; bl[2 * p][1] = t[1];
                    bl[2 * p + 1][0] = t[2]; bl[2 * p + 1][1] = t[3];
                }
#pragma unroll
                for (int nt = 0; nt < 8; nt++) {
                    MMA_BF16(c[nt], ah, bh[nt]);
                    MMA_BF16(c[nt], ah, bl[nt]);
                    MMA_BF16(c[nt], al, bh[nt]);
                }
            }

            float mx0 = -1e30f, mx1 = -1e30f;
#pragma unroll
            for (int nt = 0; nt < 8; nt++) {
                int col = kb * 64 + nt * 8 + ec;
#pragma unroll
                for (int j = 0; j < 2; j++) {
                    float s0 = c[nt][j] * SCL;
                    float s1 = c[nt][j + 2] * SCL;
                    if (col + j > grow_lo) s0 = -1e30f;
                    if (col + j > grow_hi) s1 = -1e30f;
                    c[nt][j] = s0; c[nt][j + 2] = s1;
                    mx0 = fmaxf(mx0, s0); mx1 = fmaxf(mx1, s1);
                }
            }
            mx0 = fmaxf(mx0, __shfl_xor_sync(0xffffffffu, mx0, 1));
            mx0 = fmaxf(mx0, __shfl_xor_sync(0xffffffffu, mx0, 2));
            mx1 = fmaxf(mx1, __shfl_xor_sync(0xffffffffu, mx1, 1));
            mx1 = fmaxf(mx1, __shfl_xor_sync(0xffffffffu, mx1, 2));
            float m0n = fmaxf(m0, mx0), m1n = fmaxf(m1, mx1);
            float a0 = ex2(m0 - m0n), a1 = ex2(m1 - m1n);
            m0 = m0n; m1 = m1n;

            float sum0 = 0.f, sum1 = 0.f;
#pragma unroll
            for (int nt = 0; nt < 8; nt++) {
                float p0 = ex2(c[nt][0] - m0n), p1 = ex2(c[nt][1] - m0n);
                float p2 = ex2(c[nt][2] - m1n), p3 = ex2(c[nt][3] - m1n);
                c[nt][0] = p0; c[nt][1] = p1; c[nt][2] = p2; c[nt][3] = p3;
                sum0 += p0 + p1; sum1 += p2 + p3;
            }
            sum0 += __shfl_xor_sync(0xffffffffu, sum0, 1);
            sum0 += __shfl_xor_sync(0xffffffffu, sum0, 2);
            sum1 += __shfl_xor_sync(0xffffffffu, sum1, 1);
            sum1 += __shfl_xor_sync(0xffffffffu, sum1, 2);
            l0 = l0 * a0 + sum0;
            l1 = l1 * a1 + sum1;
#pragma unroll
            for (int nt = 0; nt < 16; nt++) {
                o[nt][0] *= a0; o[nt][1] *= a0;
                o[nt][2] *= a1; o[nt][3] *= a1;
            }

#pragma unroll
            for (int kk = 0; kk < 4; kk++) {
                uint32_t ph[4], pl[4];
                pack_hilo(c[2 * kk][0],     c[2 * kk][1],     ph[0], pl[0]);
                pack_hilo(c[2 * kk][2],     c[2 * kk][3],     ph[1], pl[1]);
                pack_hilo(c[2 * kk + 1][0], c[2 * kk + 1][1], ph[2], pl[2]);
                pack_hilo(c[2 * kk + 1][2], c[2 * kk + 1][3], ph[3], pl[3]);
#pragma unroll
                for (int p = 0; p < 8; p++) {
                    uint32_t vh[4], vl[4];
                    uint32_t offV = (uint32_t)(((kk * 16 + l7 + k8) * QK_STR + p * 16 + n8) * 2);
                    LDM4T(vh, sVh + offV);
                    LDM4T(vl, sVl + offV);
                    uint32_t vh0[2] = {vh[0], vh[1]}, vh1[2] = {vh[2], vh[3]};
                    uint32_t vl0[2] = {vl[0], vl[1]}, vl1[2] = {vl[2], vl[3]};
                    MMA_BF16(o[2 * p], ph, vh0);
                    MMA_BF16(o[2 * p], pl, vh0);
                    MMA_BF16(o[2 * p], ph, vl0);
                    MMA_BF16(o[2 * p + 1], ph, vh1);
                    MMA_BF16(o[2 * p + 1], pl, vh1);
                    MMA_BF16(o[2 * p + 1], ph, vl1);
                }
            }
        }
        __syncthreads();
    }

    float inv0 = 1.f / l0, inv1 = 1.f / l1;
    size_t tok_lo = (bT + (size_t)grow_lo) * DMODEL + hoff;
    size_t tok_hi = (bT + (size_t)grow_hi) * DMODEL + hoff;
#pragma unroll
    for (int nt = 0; nt < 16; nt++) {
        int col = nt * 8 + ec;
        float v0 = o[nt][0] * inv0, v1 = o[nt][1] * inv0;
        float v2 = o[nt][2] * inv1, v3 = o[nt][3] * inv1;
        uint32_t h01, l01, h23, l23;
        pack_hilo(v0, v1, h01, l01);
        pack_hilo(v2, v3, h23, l23);
        *(uint32_t*)(Oh + tok_lo + col) = h01;
        *(uint32_t*)(Oh + tok_hi + col) = h23;
        *(uint32_t*)(Ol + tok_lo + col) = l01;
        *(uint32_t*)(Ol + tok_hi + col) = l23;
    }
}

// ---------------- launch ----------------------------------------------------
static inline void conv(const float* in, bf16* h, bf16* l, int n) {
    int n4 = n / 4;
    conv_hilo<<<(n4 + 255) / 256, 256>>>(in, h, l, n4);
}

extern "C" void kernel_launch(void* const* d_in, const int* in_sizes, int n_in,
                              void* d_out, int out_size) {
    const float* x      = (const float*)d_in[0];
    const float* q_a_w  = (const float*)d_in[2];
    const float* q_b_w  = (const float*)d_in[3];
    const float* kv_a_w = (const float*)d_in[4];
    const float* k_b_w  = (const float*)d_in[5];
    const float* v_b_w  = (const float*)d_in[6];
    const float* o_w    = (const float*)d_in[7];
    const float* q_nw   = (const float*)d_in[8];
    const float* k_nw   = (const float*)d_in[9];

    float *q, *k;
    bf16 *xh, *xl, *qlh, *qll, *kvh, *kvl;
    bf16 *qh, *ql, *kh, *kl, *vh, *vl, *aoh, *aol;
    bf16 *wqah, *wqal, *wqbh, *wqbl, *wkvh, *wkvl, *wkbh, *wkbl, *wvbh, *wvbl, *owh, *owl;
    cudaGetSymbolAddress((void**)&q, g_q);     cudaGetSymbolAddress((void**)&k, g_k);
    cudaGetSymbolAddress((void**)&xh, g_xh);   cudaGetSymbolAddress((void**)&xl, g_xl);
    cudaGetSymbolAddress((void**)&qlh, g_qlh); cudaGetSymbolAddress((void**)&qll, g_qll);
    cudaGetSymbolAddress((void**)&kvh, g_kvh); cudaGetSymbolAddress((void**)&kvl, g_kvl);
    cudaGetSymbolAddress((void**)&qh, g_qh);   cudaGetSymbolAddress((void**)&ql, g_ql);
    cudaGetSymbolAddress((void**)&kh, g_kh);   cudaGetSymbolAddress((void**)&kl, g_kl);
    cudaGetSymbolAddress((void**)&vh, g_vh);   cudaGetSymbolAddress((void**)&vl, g_vl);
    cudaGetSymbolAddress((void**)&aoh, g_aoh); cudaGetSymbolAddress((void**)&aol, g_aol);
    cudaGetSymbolAddress((void**)&wqah, g_wqah); cudaGetSymbolAddress((void**)&wqal, g_wqal);
    cudaGetSymbolAddress((void**)&wqbh, g_wqbh); cudaGetSymbolAddress((void**)&wqbl, g_wqbl);
    cudaGetSymbolAddress((void**)&wkvh, g_wkvh); cudaGetSymbolAddress((void**)&wkvl, g_wkvl);
    cudaGetSymbolAddress((void**)&wkbh, g_wkbh); cudaGetSymbolAddress((void**)&wkbl, g_wkbl);
    cudaGetSymbolAddress((void**)&wvbh, g_wvbh); cudaGetSymbolAddress((void**)&wvbl, g_wvbl);
    cudaGetSymbolAddress((void**)&owh, g_owh);   cudaGetSymbolAddress((void**)&owl, g_owl);

    cudaFuncSetAttribute(gemm_mma, cudaFuncAttributeMaxDynamicSharedMemorySize,
                         GEMM_SMEM_BYTES);
    cudaFuncSetAttribute(flash_mma, cudaFuncAttributeMaxDynamicSharedMemorySize,
                         FLASH_SMEM_BYTES);

    // fp32 -> bf16 hi/lo conversions
    conv(x, xh, xl, TOKENS * DMODEL);
    conv(q_a_w, wqah, wqal, QLATD * DMODEL);
    conv(q_b_w, wqbh, wqbl, DMODEL * QLATD);
    conv(kv_a_w, wkvh, wkvl, KVLATD * DMODEL);
    conv(k_b_w, wkbh, wkbl, DMODEL * KVLATD);
    conv(v_b_w, wvbh, wvbl, DMODEL * KVLATD);
    conv(o_w, owh, owl, DMODEL * DMODEL);

    // projections on HMMA (3-term bf16 split, cp.async pipelined, fat tiles)
    gemm_mma<<<dim3(QLATD / 128, TOKENS / 128), 128, GEMM_SMEM_BYTES>>>(
        xh, xl, wqah, wqal, nullptr, qlh, qll, TOKENS, QLATD, DMODEL);
    gemm_mma<<<dim3(DMODEL / 128, TOKENS / 128), 128, GEMM_SMEM_BYTES>>>(
        qlh, qll, wqbh, wqbl, q, nullptr, nullptr, TOKENS, DMODEL, QLATD);
    gemm_mma<<<dim3(KVLATD / 128, TOKENS / 128), 128, GEMM_SMEM_BYTES>>>(
        xh, xl, wkvh, wkvl, nullptr, kvh, kvl, TOKENS, KVLATD, DMODEL);
    gemm_mma<<<dim3(DMODEL / 128, TOKENS / 128), 128, GEMM_SMEM_BYTES>>>(
        kvh, kvl, wkbh, wkbl, k, nullptr, nullptr, TOKENS, DMODEL, KVLATD);
    gemm_mma<<<dim3(DMODEL / 128, TOKENS / 128), 128, GEMM_SMEM_BYTES>>>(
        kvh, kvl, wvbh, wvbl, nullptr, vh, vl, TOKENS, DMODEL, KVLATD);

    // per-head RMSNorm + RoPE -> bf16 hi/lo
    norm_rope_kernel<<<TOKENS * NHEADS, 128>>>(q, q_nw, qh, ql);
    norm_rope_kernel<<<TOKENS * NHEADS, 128>>>(k, k_nw, kh, kl);

    // causal flash attention v2 (BQ=128, register P, heavy-first order)
    flash_mma<<<dim3(TSEQ / 128, 2 * NHEADS), 256, FLASH_SMEM_BYTES>>>(
        qh, ql, kh, kl, vh, vl, aoh, aol);

    // output projection -> fp32 d_out
    gemm_mma<<<dim3(DMODEL / 128, TOKENS / 128), 128, GEMM_SMEM_BYTES>>>(
        aoh, aol, owh, owl, (float*)d_out, nullptr, nullptr, TOKENS, DMODEL, DMODEL);
}

// round 8
// speedup vs baseline: 3.5064x; 1.2626x over previous
#include <cuda_runtime.h>
#include <cuda_bf16.h>
#include <cuda_fp16.h>
#include <math.h>
#include <cstdint>

#define TOKENS 4096   // B*T
#define DMODEL 2048   // NH*HD
#define TSEQ   2048
#define NHEADS 16
#define HDIM   128
#define QLATD  1024
#define KVLATD 512

typedef __nv_bfloat16 bf16;

// ---------------- scratch (device globals; no allocation allowed) ----------
__device__ float g_q  [TOKENS * DMODEL];
__device__ float g_k  [TOKENS * DMODEL];
__device__ bf16 g_xh [TOKENS * DMODEL],  g_xl [TOKENS * DMODEL];
__device__ bf16 g_qlh[TOKENS * QLATD],   g_qll[TOKENS * QLATD];
__device__ bf16 g_kvh[TOKENS * KVLATD],  g_kvl[TOKENS * KVLATD];
__device__ bf16 g_qh [TOKENS * DMODEL],  g_ql [TOKENS * DMODEL];
__device__ bf16 g_kh [TOKENS * DMODEL],  g_kl [TOKENS * DMODEL];
__device__ half g_vf [TOKENS * DMODEL];            // V single fp16
__device__ half g_aof[TOKENS * DMODEL];            // attention out, single fp16
__device__ half g_owf[DMODEL * DMODEL];            // o_w single fp16
__device__ bf16 g_wqah[QLATD * DMODEL],  g_wqal[QLATD * DMODEL];
__device__ bf16 g_wqbh[DMODEL * QLATD],  g_wqbl[DMODEL * QLATD];
__device__ bf16 g_wkvh[KVLATD * DMODEL], g_wkvl[KVLATD * DMODEL];
__device__ bf16 g_wkbh[DMODEL * KVLATD], g_wkbl[DMODEL * KVLATD];
__device__ bf16 g_wvbh[DMODEL * KVLATD], g_wvbl[DMODEL * KVLATD];

// ================= helpers (baseline PTX, no "a"-features) =================
__device__ __forceinline__ uint32_t smem_u32(const void* p) {
    uint32_t a;
    asm("{ .reg .u64 t; cvta.to.shared.u64 t, %1; cvt.u32.u64 %0, t; }"
        : "=r"(a) : "l"(p));
    return a;
}
__device__ __forceinline__ float ex2(float x) {
    float y;
    asm("ex2.approx.ftz.f32 %0, %1;" : "=f"(y) : "f"(x));
    return y;
}

#define CP_ASYNC16(sa, gp) \
    asm volatile("cp.async.cg.shared.global [%0], [%1], 16;" :: "r"(sa), "l"(gp))
#define CP_COMMIT() asm volatile("cp.async.commit_group;" ::: "memory")
#define CP_WAIT0()  asm volatile("cp.async.wait_group 0;" ::: "memory")
#define CP_WAIT1()  asm volatile("cp.async.wait_group 1;" ::: "memory")

#define LDM4(r, addr) \
    asm volatile("ldmatrix.sync.aligned.m8n8.x4.shared.b16 {%0,%1,%2,%3}, [%4];" \
                 : "=r"((r)[0]), "=r"((r)[1]), "=r"((r)[2]), "=r"((r)[3]) : "r"(addr))
#define LDM4T(r, addr) \
    asm volatile("ldmatrix.sync.aligned.m8n8.x4.trans.shared.b16 {%0,%1,%2,%3}, [%4];" \
                 : "=r"((r)[0]), "=r"((r)[1]), "=r"((r)[2]), "=r"((r)[3]) : "r"(addr))
#define MMA_BF16(d, a, b) \
    asm volatile("mma.sync.aligned.m16n8k16.row.col.f32.bf16.bf16.f32 " \
                 "{%0,%1,%2,%3}, {%4,%5,%6,%7}, {%8,%9}, {%0,%1,%2,%3};" \
                 : "+f"((d)[0]), "+f"((d)[1]), "+f"((d)[2]), "+f"((d)[3]) \
                 : "r"((a)[0]), "r"((a)[1]), "r"((a)[2]), "r"((a)[3]), \
                   "r"((b)[0]), "r"((b)[1]))
#define MMA_F16(d, a, b) \
    asm volatile("mma.sync.aligned.m16n8k16.row.col.f32.f16.f16.f32 " \
                 "{%0,%1,%2,%3}, {%4,%5,%6,%7}, {%8,%9}, {%0,%1,%2,%3};" \
                 : "+f"((d)[0]), "+f"((d)[1]), "+f"((d)[2]), "+f"((d)[3]) \
                 : "r"((a)[0]), "r"((a)[1]), "r"((a)[2]), "r"((a)[3]), \
                   "r"((b)[0]), "r"((b)[1]))

__device__ __forceinline__ void split2(float v, bf16& h, bf16& l) {
    h = __float2bfloat16_rn(v);
    l = __float2bfloat16_rn(v - __bfloat162float(h));
}
__device__ __forceinline__ void pack_hilo(float a, float b, uint32_t& h, uint32_t& l) {
    bf16 ha, la, hb, lb;
    split2(a, ha, la);
    split2(b, hb, lb);
    __nv_bfloat162 th(ha, hb), tl(la, lb);
    h = *(uint32_t*)&th;
    l = *(uint32_t*)&tl;
}
__device__ __forceinline__ uint32_t pack_h2(float a, float b) {
    __half2 t = __floats2half2_rn(a, b);
    return *(uint32_t*)&t;
}

// ============= 3-term bf16 GEMM: C = (Ah+Al)(Bh+Bl)^T, 4 warps 64x64 =======
#define SSTR 40
#define G_ARR  10240
#define G_STG  (4 * G_ARR)
#define GEMM_SMEM_BYTES (2 * G_STG)

__global__ __launch_bounds__(128)
void gemm_mma(const bf16* __restrict__ Ah, const bf16* __restrict__ Al,
              const bf16* __restrict__ Bh, const bf16* __restrict__ Bl,
              float* __restrict__ Cf, bf16* __restrict__ Ch,
              bf16* __restrict__ Cl, half* __restrict__ Cf16,
              int M, int N, int K) {
    extern __shared__ bf16 sg[];
    const uint32_t sb = smem_u32(sg);

    const int tid = threadIdx.x, lane = tid & 31, warp = tid >> 5;
    const int wm = (warp & 1) * 64, wn = (warp >> 1) * 64;
    const int bm = blockIdx.y * 128, bn = blockIdx.x * 128;

    const int lrA = lane & 15, lcA = (lane >> 4) << 3;
    const int l7 = lane & 7;
    const int k8 = ((lane >> 3) & 1) << 3;
    const int n8 = ((lane >> 4) & 1) << 3;

    float c[4][8][4];
#pragma unroll
    for (int i = 0; i < 4; i++)
#pragma unroll
        for (int j = 0; j < 8; j++)
#pragma unroll
            for (int k = 0; k < 4; k++) c[i][j][k] = 0.f;

    auto load_stage = [&](int kt, int s) {
        uint32_t so = sb + (uint32_t)s * G_STG;
#pragma unroll
        for (int i = 0; i < 4; i++) {
            int idx = tid + i * 128;
            int row = idx >> 2, cc = idx & 3;
            size_t gA = (size_t)(bm + row) * K + kt + cc * 8;
            size_t gB = (size_t)(bn + row) * K + kt + cc * 8;
            uint32_t off = (uint32_t)(row * (SSTR * 2) + cc * 16);
            CP_ASYNC16(so + off,             Ah + gA);
            CP_ASYNC16(so + G_ARR + off,     Al + gA);
            CP_ASYNC16(so + 2 * G_ARR + off, Bh + gB);
            CP_ASYNC16(so + 3 * G_ARR + off, Bl + gB);
        }
    };

    const int nkt = K >> 5;
    load_stage(0, 0);
    CP_COMMIT();

    for (int kt = 0; kt < nkt; kt++) {
        if (kt + 1 < nkt) {
            load_stage((kt + 1) << 5, (kt + 1) & 1);
            CP_COMMIT();
            CP_WAIT1();
        } else {
            CP_WAIT0();
        }
        __syncthreads();

        const uint32_t aAh = sb + (uint32_t)(kt & 1) * G_STG;
        const uint32_t aAl = aAh + G_ARR;
        const uint32_t aBh = aAh + 2 * G_ARR;
        const uint32_t aBl = aAh + 3 * G_ARR;

#pragma unroll
        for (int ks = 0; ks < 32; ks += 16) {
            uint32_t bh[8][2], bl[8][2], t[4];
#pragma unroll
            for (int p = 0; p < 4; p++) {
                uint32_t off = (uint32_t)(((wn + p * 16 + n8 + l7) * SSTR + ks + k8) * 2);
                LDM4(t, aBh + off);
                bh[2 * p][0] = t[0]; bh[2 * p][1] = t[1];
                bh[2 * p + 1][0] = t[2]; bh[2 * p + 1][1] = t[3];
                LDM4(t, aBl + off);
                bl[2 * p][0] = t[0]; bl[2 * p][1] = t[1];
                bl[2 * p + 1][0] = t[2]; bl[2 * p + 1][1] = t[3];
            }
#pragma unroll
            for (int mt = 0; mt < 4; mt++) {
                uint32_t off = (uint32_t)(((wm + mt * 16 + lrA) * SSTR + ks + lcA) * 2);
                uint32_t ah[4], al[4];
                LDM4(ah, aAh + off);
                LDM4(al, aAl + off);
#pragma unroll
                for (int nt = 0; nt < 8; nt++) {
                    MMA_BF16(c[mt][nt], ah, bh[nt]);
                    MMA_BF16(c[mt][nt], ah, bl[nt]);
                    MMA_BF16(c[mt][nt], al, bh[nt]);
                }
            }
        }
        __syncthreads();
    }

    const int er = lane >> 2, ec = (lane & 3) << 1;
#pragma unroll
    for (int mt = 0; mt < 4; mt++) {
#pragma unroll
        for (int nt = 0; nt < 8; nt++) {
            size_t r0 = (size_t)(bm + wm + mt * 16 + er);
            int c0 = bn + wn + nt * 8 + ec;
            float v0 = c[mt][nt][0], v1 = c[mt][nt][1];
            float v2 = c[mt][nt][2], v3 = c[mt][nt][3];
            if (Cf) {
                *(float2*)(Cf + r0 * N + c0)       = make_float2(v0, v1);
                *(float2*)(Cf + (r0 + 8) * N + c0) = make_float2(v2, v3);
            }
            if (Ch) {
                uint32_t h01, l01, h23, l23;
                pack_hilo(v0, v1, h01, l01);
                pack_hilo(v2, v3, h23, l23);
                *(uint32_t*)(Ch + r0 * N + c0)       = h01;
                *(uint32_t*)(Ch + (r0 + 8) * N + c0) = h23;
                *(uint32_t*)(Cl + r0 * N + c0)       = l01;
                *(uint32_t*)(Cl + (r0 + 8) * N + c0) = l23;
            }
            if (Cf16) {
                *(uint32_t*)(Cf16 + r0 * N + c0)       = pack_h2(v0, v1);
                *(uint32_t*)(Cf16 + (r0 + 8) * N + c0) = pack_h2(v2, v3);
            }
        }
    }
}

// ============= single-product fp16 GEMM (for output projection) ============
#define H_ARR 10240
#define H_STG (2 * H_ARR)
#define GEMMH_SMEM_BYTES (2 * H_STG)   // 40960

__global__ __launch_bounds__(128)
void gemm_f16(const half* __restrict__ A, const half* __restrict__ B,
              float* __restrict__ Cf, int M, int N, int K) {
    extern __shared__ half sh[];
    const uint32_t sb = smem_u32(sh);

    const int tid = threadIdx.x, lane = tid & 31, warp = tid >> 5;
    const int wm = (warp & 1) * 64, wn = (warp >> 1) * 64;
    const int bm = blockIdx.y * 128, bn = blockIdx.x * 128;

    const int lrA = lane & 15, lcA = (lane >> 4) << 3;
    const int l7 = lane & 7;
    const int k8 = ((lane >> 3) & 1) << 3;
    const int n8 = ((lane >> 4) & 1) << 3;

    float c[4][8][4];
#pragma unroll
    for (int i = 0; i < 4; i++)
#pragma unroll
        for (int j = 0; j < 8; j++)
#pragma unroll
            for (int k = 0; k < 4; k++) c[i][j][k] = 0.f;

    auto load_stage = [&](int kt, int s) {
        uint32_t so = sb + (uint32_t)s * H_STG;
#pragma unroll
        for (int i = 0; i < 4; i++) {
            int idx = tid + i * 128;
            int row = idx >> 2, cc = idx & 3;
            size_t gA = (size_t)(bm + row) * K + kt + cc * 8;
            size_t gB = (size_t)(bn + row) * K + kt + cc * 8;
            uint32_t off = (uint32_t)(row * (SSTR * 2) + cc * 16);
            CP_ASYNC16(so + off,         A + gA);
            CP_ASYNC16(so + H_ARR + off, B + gB);
        }
    };

    const int nkt = K >> 5;
    load_stage(0, 0);
    CP_COMMIT();

    for (int kt = 0; kt < nkt; kt++) {
        if (kt + 1 < nkt) {
            load_stage((kt + 1) << 5, (kt + 1) & 1);
            CP_COMMIT();
            CP_WAIT1();
        } else {
            CP_WAIT0();
        }
        __syncthreads();

        const uint32_t aA = sb + (uint32_t)(kt & 1) * H_STG;
        const uint32_t aB = aA + H_ARR;

#pragma unroll
        for (int ks = 0; ks < 32; ks += 16) {
            uint32_t bh[8][2], t[4];
#pragma unroll
            for (int p = 0; p < 4; p++) {
                uint32_t off = (uint32_t)(((wn + p * 16 + n8 + l7) * SSTR + ks + k8) * 2);
                LDM4(t, aB + off);
                bh[2 * p][0] = t[0]; bh[2 * p][1] = t[1];
                bh[2 * p + 1][0] = t[2]; bh[2 * p + 1][1] = t[3];
            }
#pragma unroll
            for (int mt = 0; mt < 4; mt++) {
                uint32_t off = (uint32_t)(((wm + mt * 16 + lrA) * SSTR + ks + lcA) * 2);
                uint32_t ah[4];
                LDM4(ah, aA + off);
#pragma unroll
                for (int nt = 0; nt < 8; nt++)
                    MMA_F16(c[mt][nt], ah, bh[nt]);
            }
        }
        __syncthreads();
    }

    const int er = lane >> 2, ec = (lane & 3) << 1;
#pragma unroll
    for (int mt = 0; mt < 4; mt++) {
#pragma unroll
        for (int nt = 0; nt < 8; nt++) {
            size_t r0 = (size_t)(bm + wm + mt * 16 + er);
            int c0 = bn + wn + nt * 8 + ec;
            *(float2*)(Cf + r0 * N + c0)       = make_float2(c[mt][nt][0], c[mt][nt][1]);
            *(float2*)(Cf + (r0 + 8) * N + c0) = make_float2(c[mt][nt][2], c[mt][nt][3]);
        }
    }
}

// ---------------- fp32 -> (bf16 hi, bf16 lo) ------------------------------
__global__ __launch_bounds__(256)
void conv_hilo(const float* __restrict__ in, bf16* __restrict__ hi,
               bf16* __restrict__ lo, int n4) {
    int i = blockIdx.x * 256 + threadIdx.x;
    if (i >= n4) return;
    float4 x = ((const float4*)in)[i];
    float v[4] = {x.x, x.y, x.z, x.w};
    bf16 h[4], l[4];
#pragma unroll
    for (int j = 0; j < 4; j++) split2(v[j], h[j], l[j]);
    ((__nv_bfloat162*)hi)[i * 2]     = __nv_bfloat162(h[0], h[1]);
    ((__nv_bfloat162*)hi)[i * 2 + 1] = __nv_bfloat162(h[2], h[3]);
    ((__nv_bfloat162*)lo)[i * 2]     = __nv_bfloat162(l[0], l[1]);
    ((__nv_bfloat162*)lo)[i * 2 + 1] = __nv_bfloat162(l[2], l[3]);
}

// ---------------- fp32 -> fp16 (single) ------------------------------------
__global__ __launch_bounds__(256)
void conv_f16(const float* __restrict__ in, half* __restrict__ out, int n4) {
    int i = blockIdx.x * 256 + threadIdx.x;
    if (i >= n4) return;
    float4 x = ((const float4*)in)[i];
    ((uint32_t*)out)[i * 2]     = pack_h2(x.x, x.y);
    ((uint32_t*)out)[i * 2 + 1] = pack_h2(x.z, x.w);
}

// -------- fused per-head RMSNorm + RoPE, emitting bf16 hi/lo ---------------
__global__ __launch_bounds__(128)
void norm_rope_kernel(const float* __restrict__ X, const float* __restrict__ w,
                      bf16* __restrict__ H, bf16* __restrict__ L) {
    const int blk = blockIdx.x;
    const int token = blk >> 4, h = blk & 15;
    const int t = token & (TSEQ - 1);
    const int i = threadIdx.x;
    const size_t off = (size_t)token * DMODEL + h * HDIM + i;
    float x = X[off];
    float ss = x * x;
#pragma unroll
    for (int o = 16; o; o >>= 1)
        ss += __shfl_xor_sync(0xffffffffu, ss, o);
    __shared__ float sred[4];
    if ((i & 31) == 0) sred[i >> 5] = ss;
    __syncthreads();
    ss = sred[0] + sred[1] + sred[2] + sred[3];
    float rn = rsqrtf(ss * (1.0f / HDIM) + 1e-6f);
    float xn = x * rn * w[i];
    __shared__ float sh[HDIM];
    sh[i] = xn;
    __syncthreads();
    const int f = i & 63;
    float invf = exp2f((float)f * (-13.287712379549449f / 64.0f));
    float ang = (float)t * invf;
    float c, s;
    sincosf(ang, &s, &c);
    float partner = (i < 64) ? -sh[i + 64] : sh[i - 64];
    float out = xn * c + partner * s;
    bf16 hh, ll;
    split2(out, hh, ll);
    H[off] = hh;
    L[off] = ll;
}

// ======== causal flash attention v3: bf16-split S, single-fp16 PV ==========
// BQ=128, BKV=64, 8 warps in m, register P, warp-local softmax.
#define QK_STR 136
#define FQ_H 0
#define FQ_L 34816
#define FKV0 69632          // per-stage: Kh, Kl, Vf (fp16 single)
#define FKVS 52224
#define SK_H 0
#define SK_L 17408
#define SV_F 34816
#define FLASH_SMEM_BYTES (69632 + 2 * 52224)   // 174080
#define SCL 0.1275175f     // (1/sqrt(128)) * log2(e)

__global__ __launch_bounds__(256, 1)
void flash_mma(const bf16* __restrict__ Qh, const bf16* __restrict__ Ql,
               const bf16* __restrict__ Kh, const bf16* __restrict__ Kl,
               const half* __restrict__ Vf, half* __restrict__ Of) {
    extern __shared__ char smraw[];
    const uint32_t sb = smem_u32(smraw);

    const int qb = (TSEQ / 128 - 1) - blockIdx.x;   // heavy CTAs first
    const int pair = blockIdx.y;
    const int b = pair >> 4, h = pair & 15;
    const int tid = threadIdx.x, lane = tid & 31, warp = tid >> 5;
    const int wm = warp * 16;
    const int er = lane >> 2, ec = (lane & 3) << 1;
    const int lrA = lane & 15, lcA = (lane >> 4) << 3;
    const int l7 = lane & 7;
    const int k8 = ((lane >> 3) & 1) << 3;
    const int n8 = ((lane >> 4) & 1) << 3;

    const size_t bT = (size_t)b * TSEQ;
    const int hoff = h * HDIM;

#pragma unroll
    for (int i = 0; i < 8; i++) {
        int idx = tid + i * 256;
        int row = idx >> 4, ch = idx & 15;
        size_t g = (bT + qb * 128 + row) * DMODEL + hoff + ch * 8;
        uint32_t off = (uint32_t)(row * (QK_STR * 2) + ch * 16);
        CP_ASYNC16(sb + FQ_H + off, Qh + g);
        CP_ASYNC16(sb + FQ_L + off, Ql + g);
    }
    auto load_kv = [&](int kb, int s) {
        uint32_t so = sb + FKV0 + (uint32_t)s * FKVS;
#pragma unroll
        for (int i = 0; i < 4; i++) {
            int idx = tid + i * 256;
            int row = idx >> 4, ch = idx & 15;
            size_t g = (bT + kb * 64 + row) * DMODEL + hoff + ch * 8;
            uint32_t off = (uint32_t)(row * (QK_STR * 2) + ch * 16);
            CP_ASYNC16(so + SK_H + off, Kh + g);
            CP_ASYNC16(so + SK_L + off, Kl + g);
            CP_ASYNC16(so + SV_F + off, Vf + g);
        }
    };
    load_kv(0, 0);
    CP_COMMIT();

    float o[16][4];
#pragma unroll
    for (int i = 0; i < 16; i++)
#pragma unroll
        for (int j = 0; j < 4; j++) o[i][j] = 0.f;
    float m0 = -1e30f, m1 = -1e30f, l0 = 0.f, l1 = 0.f;

    const int grow_lo = qb * 128 + wm + er;
    const int grow_hi = grow_lo + 8;
    const int row_max = qb * 128 + wm + 15;
    const int nkb = 2 * qb + 2;

    for (int kb = 0; kb < nkb; kb++) {
        if (kb + 1 < nkb) {
            load_kv(kb + 1, (kb + 1) & 1);
            CP_COMMIT();
            CP_WAIT1();
        } else {
            CP_WAIT0();
        }
        __syncthreads();

        if (kb * 64 <= row_max) {   // causal per-warp skip
            const uint32_t sKV = sb + FKV0 + (uint32_t)(kb & 1) * FKVS;
            const uint32_t sKh = sKV + SK_H, sKl = sKV + SK_L;
            const uint32_t sV  = sKV + SV_F;

            float c[8][4];
#pragma unroll
            for (int i = 0; i < 8; i++)
#pragma unroll
                for (int j = 0; j < 4; j++) c[i][j] = 0.f;

#pragma unroll
            for (int ks = 0; ks < 8; ks++) {
                uint32_t ah[4], al[4];
                uint32_t offA = (uint32_t)(((wm + lrA) * QK_STR + ks * 16 + lcA) * 2);
                LDM4(ah, sb + FQ_H + offA);
                LDM4(al, sb + FQ_L + offA);
                uint32_t bh[8][2], bl[8][2], t[4];
#pragma unroll
                for (int p = 0; p < 4; p++) {
                    uint32_t offB = (uint32_t)(((p * 16 + n8 + l7) * QK_STR + ks * 16 + k8) * 2);
                    LDM4(t, sKh + offB);
                    bh[2 * p][0] = t[0]; bh[2 * p][1] = t[1];
                    bh[2 * p + 1][0] = t[2]; bh[2 * p + 1][1] = t[3];
                    LDM4(t, sKl + offB);
                    bl[2 * p][0] = t[0]; bl[2 * p][1] = t[1];
                    bl[2 * p + 1][0] = t[2]; bl[2 * p + 1][1] = t[3];
                }
#pragma unroll
                for (int nt = 0; nt < 8; nt++) {
                    MMA_BF16(c[nt], ah, bh[nt]);
                    MMA_BF16(c[nt], ah, bl[nt]);
                    MMA_BF16(c[nt], al, bh[nt]);
                }
            }

            float mx0 = -1e30f, mx1 = -1e30f;
#pragma unroll
            for (int nt = 0; nt < 8; nt++) {
                int col = kb * 64 + nt * 8 + ec;
#pragma unroll
                for (int j = 0; j < 2; j++) {
                    float s0 = c[nt][j] * SCL;
                    float s1 = c[nt][j + 2] * SCL;
                    if (col + j > grow_lo) s0 = -1e30f;
                    if (col + j > grow_hi) s1 = -1e30f;
                    c[nt][j] = s0; c[nt][j + 2] = s1;
                    mx0 = fmaxf(mx0, s0); mx1 = fmaxf(mx1, s1);
                }
            }
            mx0 = fmaxf(mx0, __shfl_xor_sync(0xffffffffu, mx0, 1));
            mx0 = fmaxf(mx0, __shfl_xor_sync(0xffffffffu, mx0, 2));
            mx1 = fmaxf(mx1, __shfl_xor_sync(0xffffffffu, mx1, 1));
            mx1 = fmaxf(mx1, __shfl_xor_sync(0xffffffffu, mx1, 2));
            float m0n = fmaxf(m0, mx0), m1n = fmaxf(m1, mx1);
            float a0 = ex2(m0 - m0n), a1 = ex2(m1 - m1n);
            m0 = m0n; m1 = m1n;

            float sum0 = 0.f, sum1 = 0.f;
#pragma unroll
            for (int nt = 0; nt < 8; nt++) {
                float p0 = ex2(c[nt][0] - m0n), p1 = ex2(c[nt][1] - m0n);
                float p2 = ex2(c[nt][2] - m1n), p3 = ex2(c[nt][3] - m1n);
                c[nt][0] = p0; c[nt][1] = p1; c[nt][2] = p2; c[nt][3] = p3;
                sum0 += p0 + p1; sum1 += p2 + p3;
            }
            sum0 += __shfl_xor_sync(0xffffffffu, sum0, 1);
            sum0 += __shfl_xor_sync(0xffffffffu, sum0, 2);
            sum1 += __shfl_xor_sync(0xffffffffu, sum1, 1);
            sum1 += __shfl_xor_sync(0xffffffffu, sum1, 2);
            l0 = l0 * a0 + sum0;
            l1 = l1 * a1 + sum1;
#pragma unroll
            for (int nt = 0; nt < 16; nt++) {
                o[nt][0] *= a0; o[nt][1] *= a0;
                o[nt][2] *= a1; o[nt][3] *= a1;
            }

            // ---- O += P V : P single fp16 in registers, V single fp16 ----
#pragma unroll
            for (int kk = 0; kk < 4; kk++) {
                uint32_t ph[4];
                ph[0] = pack_h2(c[2 * kk][0],     c[2 * kk][1]);
                ph[1] = pack_h2(c[2 * kk][2],     c[2 * kk][3]);
                ph[2] = pack_h2(c[2 * kk + 1][0], c[2 * kk + 1][1]);
                ph[3] = pack_h2(c[2 * kk + 1][2], c[2 * kk + 1][3]);
#pragma unroll
                for (int p = 0; p < 8; p++) {
                    uint32_t vh[4];
                    uint32_t offV = (uint32_t)(((kk * 16 + l7 + k8) * QK_STR + p * 16 + n8) * 2);
                    LDM4T(vh, sV + offV);
                    uint32_t vh0[2] = {vh[0], vh[1]}, vh1[2] = {vh[2], vh[3]};
                    MMA_F16(o[2 * p], ph, vh0);
                    MMA_F16(o[2 * p + 1], ph, vh1);
                }
            }
        }
        __syncthreads();
    }

    float inv0 = 1.f / l0, inv1 = 1.f / l1;
    size_t tok_lo = (bT + (size_t)grow_lo) * DMODEL + hoff;
    size_t tok_hi = (bT + (size_t)grow_hi) * DMODEL + hoff;
#pragma unroll
    for (int nt = 0; nt < 16; nt++) {
        int col = nt * 8 + ec;
        *(uint32_t*)(Of + tok_lo + col) = pack_h2(o[nt][0] * inv0, o[nt][1] * inv0);
        *(uint32_t*)(Of + tok_hi + col) = pack_h2(o[nt][2] * inv1, o[nt][3] * inv1);
    }
}

// ---------------- launch ----------------------------------------------------
static inline void conv(const float* in, bf16* h, bf16* l, int n) {
    int n4 = n / 4;
    conv_hilo<<<(n4 + 255) / 256, 256>>>(in, h, l, n4);
}

extern "C" void kernel_launch(void* const* d_in, const int* in_sizes, int n_in,
                              void* d_out, int out_size) {
    const float* x      = (const float*)d_in[0];
    const float* q_a_w  = (const float*)d_in[2];
    const float* q_b_w  = (const float*)d_in[3];
    const float* kv_a_w = (const float*)d_in[4];
    const float* k_b_w  = (const float*)d_in[5];
    const float* v_b_w  = (const float*)d_in[6];
    const float* o_w    = (const float*)d_in[7];
    const float* q_nw   = (const float*)d_in[8];
    const float* k_nw   = (const float*)d_in[9];

    float *q, *k;
    bf16 *xh, *xl, *qlh, *qll, *kvh, *kvl, *qh, *ql, *kh, *kl;
    half *vf, *aof, *owf;
    bf16 *wqah, *wqal, *wqbh, *wqbl, *wkvh, *wkvl, *wkbh, *wkbl, *wvbh, *wvbl;
    cudaGetSymbolAddress((void**)&q, g_q);     cudaGetSymbolAddress((void**)&k, g_k);
    cudaGetSymbolAddress((void**)&xh, g_xh);   cudaGetSymbolAddress((void**)&xl, g_xl);
    cudaGetSymbolAddress((void**)&qlh, g_qlh); cudaGetSymbolAddress((void**)&qll, g_qll);
    cudaGetSymbolAddress((void**)&kvh, g_kvh); cudaGetSymbolAddress((void**)&kvl, g_kvl);
    cudaGetSymbolAddress((void**)&qh, g_qh);   cudaGetSymbolAddress((void**)&ql, g_ql);
    cudaGetSymbolAddress((void**)&kh, g_kh);   cudaGetSymbolAddress((void**)&kl, g_kl);
    cudaGetSymbolAddress((void**)&vf, g_vf);
    cudaGetSymbolAddress((void**)&aof, g_aof);
    cudaGetSymbolAddress((void**)&owf, g_owf);
    cudaGetSymbolAddress((void**)&wqah, g_wqah); cudaGetSymbolAddress((void**)&wqal, g_wqal);
    cudaGetSymbolAddress((void**)&wqbh, g_wqbh); cudaGetSymbolAddress((void**)&wqbl, g_wqbl);
    cudaGetSymbolAddress((void**)&wkvh, g_wkvh); cudaGetSymbolAddress((void**)&wkvl, g_wkvl);
    cudaGetSymbolAddress((void**)&wkbh, g_wkbh); cudaGetSymbolAddress((void**)&wkbl, g_wkbl);
    cudaGetSymbolAddress((void**)&wvbh, g_wvbh); cudaGetSymbolAddress((void**)&wvbl, g_wvbl);

    cudaFuncSetAttribute(gemm_mma, cudaFuncAttributeMaxDynamicSharedMemorySize,
                         GEMM_SMEM_BYTES);
    cudaFuncSetAttribute(gemm_f16, cudaFuncAttributeMaxDynamicSharedMemorySize,
                         GEMMH_SMEM_BYTES);
    cudaFuncSetAttribute(flash_mma, cudaFuncAttributeMaxDynamicSharedMemorySize,
                         FLASH_SMEM_BYTES);

    // conversions
    conv(x, xh, xl, TOKENS * DMODEL);
    conv(q_a_w, wqah, wqal, QLATD * DMODEL);
    conv(q_b_w, wqbh, wqbl, DMODEL * QLATD);
    conv(kv_a_w, wkvh, wkvl, KVLATD * DMODEL);
    conv(k_b_w, wkbh, wkbl, DMODEL * KVLATD);
    conv(v_b_w, wvbh, wvbl, DMODEL * KVLATD);
    conv_f16<<<(DMODEL * DMODEL / 4 + 255) / 256, 256>>>(o_w, owf, DMODEL * DMODEL / 4);

    // projections (3-term bf16 split)
    gemm_mma<<<dim3(QLATD / 128, TOKENS / 128), 128, GEMM_SMEM_BYTES>>>(
        xh, xl, wqah, wqal, nullptr, qlh, qll, nullptr, TOKENS, QLATD, DMODEL);
    gemm_mma<<<dim3(DMODEL / 128, TOKENS / 128), 128, GEMM_SMEM_BYTES>>>(
        qlh, qll, wqbh, wqbl, q, nullptr, nullptr, nullptr, TOKENS, DMODEL, QLATD);
    gemm_mma<<<dim3(KVLATD / 128, TOKENS / 128), 128, GEMM_SMEM_BYTES>>>(
        xh, xl, wkvh, wkvl, nullptr, kvh, kvl, nullptr, TOKENS, KVLATD, DMODEL);
    gemm_mma<<<dim3(DMODEL / 128, TOKENS / 128), 128, GEMM_SMEM_BYTES>>>(
        kvh, kvl, wkbh, wkbl, k, nullptr, nullptr, nullptr, TOKENS, DMODEL, KVLATD);
    gemm_mma<<<dim3(DMODEL / 128, TOKENS / 128), 128, GEMM_SMEM_BYTES>>>(
        kvh, kvl, wvbh, wvbl, nullptr, nullptr, nullptr, vf, TOKENS, DMODEL, KVLATD);

    // per-head RMSNorm + RoPE -> bf16 hi/lo
    norm_rope_kernel<<<TOKENS * NHEADS, 128>>>(q, q_nw, qh, ql);
    norm_rope_kernel<<<TOKENS * NHEADS, 128>>>(k, k_nw, kh, kl);

    // flash attention: bf16-split S, single-fp16 PV -> fp16 attention out
    flash_mma<<<dim3(TSEQ / 128, 2 * NHEADS), 256, FLASH_SMEM_BYTES>>>(
        qh, ql, kh, kl, vf, aof);

    // output projection: single-product fp16 -> fp32 d_out
    gemm_f16<<<dim3(DMODEL / 128, TOKENS / 128), 128, GEMMH_SMEM_BYTES>>>(
        aof, owf, (float*)d_out, TOKENS, DMODEL, DMODEL);
}